// round 1
// baseline (speedup 1.0000x reference)
#include <cuda_runtime.h>
#include <math.h>

#define NB 65536
#define ND 256
#define NE 16
#define NH 256
#define NO 256
#define NG 1024

// ---------------- scratch (device globals: no allocations allowed) ----------------
__device__ float g_h1[(size_t)NB * NG];   // 256 MB gate hidden 1
__device__ float g_h2[(size_t)NB * ND];   // 64 MB gate hidden 2
__device__ int   g_e0[NB], g_e1[NB];
__device__ float g_w0[NB], g_w1[NB];
__device__ int   g_counts[NE], g_offsets[NE], g_cursor[NE];
__device__ int   g_ptok[2 * NB];
__device__ float g_pw[2 * NB];

__global__ void zero_counts_kernel() {
    if (threadIdx.x < NE) g_counts[threadIdx.x] = 0;
}

// ---------------- generic tiled GEMM: C = op(A @ B + bias) ----------------
// BM=128 BN=64 BK=16, 256 threads (16x16), each thread 8x4 outputs.
template<bool RELU>
__global__ __launch_bounds__(256) void gemm_bias_kernel(
    const float* __restrict__ A, const float* __restrict__ Bm,
    const float* __restrict__ bias, float* __restrict__ C,
    int M, int N, int K) {
    __shared__ float As[16][132];   // transposed A tile [k][m], padded
    __shared__ float Bs[16][68];    // B tile [k][n], padded
    const int tid = threadIdx.x;
    const int tx = tid & 15, ty = tid >> 4;
    const int bm = blockIdx.y * 128;
    const int bn = blockIdx.x * 64;

    float acc[8][4];
#pragma unroll
    for (int i = 0; i < 8; i++)
#pragma unroll
        for (int j = 0; j < 4; j++) acc[i][j] = 0.f;

    for (int k0 = 0; k0 < K; k0 += 16) {
        // load A tile (2048 floats = 512 float4), store transposed
#pragma unroll
        for (int i = 0; i < 2; i++) {
            int idx = tid * 2 + i;          // 0..511
            int row = idx >> 2;             // 0..127
            int c4 = (idx & 3) * 4;         // 0,4,8,12
            float4 v = *(const float4*)(A + (size_t)(bm + row) * K + k0 + c4);
            As[c4 + 0][row] = v.x;
            As[c4 + 1][row] = v.y;
            As[c4 + 2][row] = v.z;
            As[c4 + 3][row] = v.w;
        }
        // load B tile (1024 floats = 256 float4)
        {
            int row = tid >> 4;             // 0..15
            int c4 = (tid & 15) * 4;        // 0..60
            *(float4*)&Bs[row][c4] =
                *(const float4*)(Bm + (size_t)(k0 + row) * N + bn + c4);
        }
        __syncthreads();
#pragma unroll
        for (int kk = 0; kk < 16; kk++) {
            float4 a0 = *(const float4*)&As[kk][ty * 8];
            float4 a1 = *(const float4*)&As[kk][ty * 8 + 4];
            float4 b  = *(const float4*)&Bs[kk][tx * 4];
            float a[8] = {a0.x, a0.y, a0.z, a0.w, a1.x, a1.y, a1.z, a1.w};
            float bb[4] = {b.x, b.y, b.z, b.w};
#pragma unroll
            for (int i = 0; i < 8; i++)
#pragma unroll
                for (int j = 0; j < 4; j++)
                    acc[i][j] += a[i] * bb[j];
        }
        __syncthreads();
    }

    float4 bv = *(const float4*)(bias + bn + tx * 4);
#pragma unroll
    for (int i = 0; i < 8; i++) {
        float4 o;
        o.x = acc[i][0] + bv.x;
        o.y = acc[i][1] + bv.y;
        o.z = acc[i][2] + bv.z;
        o.w = acc[i][3] + bv.w;
        if (RELU) {
            o.x = fmaxf(o.x, 0.f); o.y = fmaxf(o.y, 0.f);
            o.z = fmaxf(o.z, 0.f); o.w = fmaxf(o.w, 0.f);
        }
        *(float4*)(C + (size_t)(bm + ty * 8 + i) * N + bn + tx * 4) = o;
    }
}

// ---------------- gate head: logits -> softmax -> top2 -> p + routing ----------------
// one warp per token, 8 tokens per block
__global__ __launch_bounds__(256) void gate3_kernel(
    const float* __restrict__ h2, const float* __restrict__ g3,
    const float* __restrict__ gb3, float* __restrict__ p_out) {
    __shared__ float sg3t[16][260];  // g3 transposed [e][k], padded
    __shared__ float sh2[8][256];
    const int tid = threadIdx.x;
    const int warp = tid >> 5, lane = tid & 31;

    for (int idx = tid; idx < ND * NE; idx += 256)
        sg3t[idx & 15][idx >> 4] = g3[idx];

    const int t = blockIdx.x * 8 + warp;
    const float4* hrow = (const float4*)(h2 + (size_t)t * ND);
    for (int i = lane; i < ND / 4; i += 32)
        *(float4*)&sh2[warp][i * 4] = hrow[i];
    __syncthreads();

    float logit = -1e30f;
    if (lane < 16) {
        float s = gb3[lane];
#pragma unroll 8
        for (int k4 = 0; k4 < ND / 4; k4++) {
            float4 hv = *(const float4*)&sh2[warp][k4 * 4];
            float4 gv = *(const float4*)&sg3t[lane][k4 * 4];
            s += hv.x * gv.x + hv.y * gv.y + hv.z * gv.z + hv.w * gv.w;
        }
        logit = s;
    }
    // softmax over lanes 0..15 (width-16 shuffle groups; upper half harmless)
    float mx = logit;
#pragma unroll
    for (int m = 8; m >= 1; m >>= 1)
        mx = fmaxf(mx, __shfl_xor_sync(0xffffffffu, mx, m, 16));
    float ex = expf(logit - mx);
    float sum = ex;
#pragma unroll
    for (int m = 8; m >= 1; m >>= 1)
        sum += __shfl_xor_sync(0xffffffffu, sum, m, 16);
    float pv = ex / sum;

    // top-1 (lowest index wins ties, matching jax top_k)
    float v1 = pv; int i1 = lane & 15;
#pragma unroll
    for (int m = 8; m >= 1; m >>= 1) {
        float ov = __shfl_xor_sync(0xffffffffu, v1, m, 16);
        int   oi = __shfl_xor_sync(0xffffffffu, i1, m, 16);
        if (ov > v1 || (ov == v1 && oi < i1)) { v1 = ov; i1 = oi; }
    }
    // top-2
    float c2 = ((lane & 15) == i1) ? -1.f : pv;
    float v2 = c2; int i2 = lane & 15;
#pragma unroll
    for (int m = 8; m >= 1; m >>= 1) {
        float ov = __shfl_xor_sync(0xffffffffu, v2, m, 16);
        int   oi = __shfl_xor_sync(0xffffffffu, i2, m, 16);
        if (ov > v2 || (ov == v2 && oi < i2)) { v2 = ov; i2 = oi; }
    }
    float inv = 1.f / (v1 + v2 + 1e-9f);
    if (lane < 16) {
        float po = 0.f;
        if (lane == i1) po = v1 * inv;
        else if (lane == i2) po = v2 * inv;
        p_out[(size_t)t * NE + lane] = po;
    }
    if (lane == 0) {
        g_e0[t] = i1; g_e1[t] = i2;
        g_w0[t] = v1 * inv; g_w1[t] = v2 * inv;
        atomicAdd(&g_counts[i1], 1);
        atomicAdd(&g_counts[i2], 1);
    }
}

__global__ void scan_kernel() {
    if (threadIdx.x == 0) {
        int off = 0;
#pragma unroll
        for (int e = 0; e < NE; e++) {
            g_offsets[e] = off;
            g_cursor[e] = off;
            off += g_counts[e];
        }
    }
}

__global__ __launch_bounds__(256) void scatter_kernel() {
    int t = blockIdx.x * 256 + threadIdx.x;
    int e0 = g_e0[t], e1 = g_e1[t];
    int p0 = atomicAdd(&g_cursor[e0], 1);
    g_ptok[p0] = t; g_pw[p0] = g_w0[t];
    int p1 = atomicAdd(&g_cursor[e1], 1);
    g_ptok[p1] = t; g_pw[p1] = g_w1[t];
}

// ---------------- expert kernel: 64-token tile, 2 fused smem GEMMs ----------------
#define XB_LD 260
#define W_LD 68
#define EXPERT_SMEM ((2 * 64 * XB_LD + 64 * W_LD) * 4)   // 150528 B

__global__ __launch_bounds__(256) void expert_kernel(
    const float* __restrict__ x, const float* __restrict__ bias,
    const float* __restrict__ W1, const float* __restrict__ b1,
    const float* __restrict__ W2, const float* __restrict__ b2,
    float* __restrict__ y) {
    const int e = blockIdx.y;
    const int cnt = g_counts[e];
    const int start = blockIdx.x * 64;
    if (start >= cnt) return;
    const int base = g_offsets[e];
    const int valid = min(64, cnt - start);

    extern __shared__ float smem[];
    float* s_xb = smem;                    // [64][260]
    float* s_he = smem + 64 * XB_LD;       // [64][260]
    float* s_w  = smem + 2 * 64 * XB_LD;   // [64][68]
    __shared__ int   s_tok[64];
    __shared__ float s_gw[64];

    const int tid = threadIdx.x;
    const int tx = tid & 15, ty = tid >> 4;

    if (tid < 64) {
        int tok = 0; float w = 0.f;
        if (tid < valid) { tok = g_ptok[base + start + tid]; w = g_pw[base + start + tid]; }
        s_tok[tid] = tok; s_gw[tid] = w;
    }
    __syncthreads();

    // gather xb = x[tok] + bias[e]  (64 x 256, float4)
#pragma unroll
    for (int i = 0; i < 16; i++) {
        int idx = tid + i * 256;
        int row = idx >> 6;
        int c4 = (idx & 63) * 4;
        int tok = s_tok[row];
        float4 xv = *(const float4*)(x + (size_t)tok * ND + c4);
        float4 bv = *(const float4*)(bias + (size_t)e * ND + c4);
        *(float4*)&s_xb[row * XB_LD + c4] =
            make_float4(xv.x + bv.x, xv.y + bv.y, xv.z + bv.z, xv.w + bv.w);
    }
    __syncthreads();

    // GEMM1: he = relu(xb @ W1[e] + b1[e]), chunked 64 over H
    const float* W1e = W1 + (size_t)e * ND * NH;
    for (int h0 = 0; h0 < NH; h0 += 64) {
        float acc[4][4];
#pragma unroll
        for (int i = 0; i < 4; i++)
#pragma unroll
            for (int j = 0; j < 4; j++) acc[i][j] = 0.f;
        for (int k0 = 0; k0 < ND; k0 += 64) {
#pragma unroll
            for (int i = 0; i < 4; i++) {
                int idx = tid + i * 256;
                int row = idx >> 4;
                int c4 = (idx & 15) * 4;
                *(float4*)&s_w[row * W_LD + c4] =
                    *(const float4*)(W1e + (size_t)(k0 + row) * NH + h0 + c4);
            }
            __syncthreads();
#pragma unroll
            for (int kk = 0; kk < 64; kk++) {
                float a[4];
#pragma unroll
                for (int i = 0; i < 4; i++) a[i] = s_xb[(ty * 4 + i) * XB_LD + k0 + kk];
                float4 b = *(const float4*)&s_w[kk * W_LD + tx * 4];
#pragma unroll
                for (int i = 0; i < 4; i++) {
                    acc[i][0] += a[i] * b.x; acc[i][1] += a[i] * b.y;
                    acc[i][2] += a[i] * b.z; acc[i][3] += a[i] * b.w;
                }
            }
            __syncthreads();
        }
        float4 b1v = *(const float4*)(b1 + (size_t)e * NH + h0 + tx * 4);
#pragma unroll
        for (int i = 0; i < 4; i++) {
            float4 o;
            o.x = fmaxf(acc[i][0] + b1v.x, 0.f);
            o.y = fmaxf(acc[i][1] + b1v.y, 0.f);
            o.z = fmaxf(acc[i][2] + b1v.z, 0.f);
            o.w = fmaxf(acc[i][3] + b1v.w, 0.f);
            *(float4*)&s_he[(ty * 4 + i) * XB_LD + h0 + tx * 4] = o;
        }
    }
    // (s_he writes are ordered before GEMM2 inner reads by the sync after the
    //  first s_w load of GEMM2)

    // GEMM2: out = (he @ W2[e] + b2[e]) * gate_w -> atomicAdd y
    const float* W2e = W2 + (size_t)e * NH * NO;
    for (int o0 = 0; o0 < NO; o0 += 64) {
        float acc[4][4];
#pragma unroll
        for (int i = 0; i < 4; i++)
#pragma unroll
            for (int j = 0; j < 4; j++) acc[i][j] = 0.f;
        for (int k0 = 0; k0 < NH; k0 += 64) {
#pragma unroll
            for (int i = 0; i < 4; i++) {
                int idx = tid + i * 256;
                int row = idx >> 4;
                int c4 = (idx & 15) * 4;
                *(float4*)&s_w[row * W_LD + c4] =
                    *(const float4*)(W2e + (size_t)(k0 + row) * NO + o0 + c4);
            }
            __syncthreads();
#pragma unroll
            for (int kk = 0; kk < 64; kk++) {
                float a[4];
#pragma unroll
                for (int i = 0; i < 4; i++) a[i] = s_he[(ty * 4 + i) * XB_LD + k0 + kk];
                float4 b = *(const float4*)&s_w[kk * W_LD + tx * 4];
#pragma unroll
                for (int i = 0; i < 4; i++) {
                    acc[i][0] += a[i] * b.x; acc[i][1] += a[i] * b.y;
                    acc[i][2] += a[i] * b.z; acc[i][3] += a[i] * b.w;
                }
            }
            __syncthreads();
        }
        float4 b2v = *(const float4*)(b2 + (size_t)e * NO + o0 + tx * 4);
#pragma unroll
        for (int i = 0; i < 4; i++) {
            int r = ty * 4 + i;
            if (r < valid) {
                float gw = s_gw[r];
                float* yb = y + (size_t)s_tok[r] * NO + o0 + tx * 4;
                atomicAdd(yb + 0, (acc[i][0] + b2v.x) * gw);
                atomicAdd(yb + 1, (acc[i][1] + b2v.y) * gw);
                atomicAdd(yb + 2, (acc[i][2] + b2v.z) * gw);
                atomicAdd(yb + 3, (acc[i][3] + b2v.w) * gw);
            }
        }
    }
}

// ---------------- launch ----------------
extern "C" void kernel_launch(void* const* d_in, const int* in_sizes, int n_in,
                              void* d_out, int out_size) {
    const float* x    = (const float*)d_in[0];
    const float* bias = (const float*)d_in[1];
    const float* W1   = (const float*)d_in[2];
    const float* b1   = (const float*)d_in[3];
    const float* W2   = (const float*)d_in[4];
    const float* b2   = (const float*)d_in[5];
    const float* g1   = (const float*)d_in[6];
    const float* gb1  = (const float*)d_in[7];
    const float* g2   = (const float*)d_in[8];
    const float* gb2  = (const float*)d_in[9];
    const float* g3   = (const float*)d_in[10];
    const float* gb3  = (const float*)d_in[11];

    float* yout = (float*)d_out;                    // [B, O]
    float* pout = yout + (size_t)NB * NO;           // [B, E]

    float *h1p = nullptr, *h2p = nullptr;
    cudaGetSymbolAddress((void**)&h1p, g_h1);
    cudaGetSymbolAddress((void**)&h2p, g_h2);
    cudaFuncSetAttribute(expert_kernel,
                         cudaFuncAttributeMaxDynamicSharedMemorySize, EXPERT_SMEM);

    cudaMemsetAsync(yout, 0, (size_t)NB * NO * sizeof(float), 0);
    zero_counts_kernel<<<1, 32>>>();

    // gate MLP
    gemm_bias_kernel<true><<<dim3(NG / 64, NB / 128), 256>>>(x,  g1, gb1, h1p, NB, NG, ND);
    gemm_bias_kernel<true><<<dim3(ND / 64, NB / 128), 256>>>(h1p, g2, gb2, h2p, NB, ND, NG);
    gate3_kernel<<<NB / 8, 256>>>(h2p, g3, gb3, pout);

    // routing
    scan_kernel<<<1, 32>>>();
    scatter_kernel<<<NB / 256, 256>>>();

    // top-2 expert compute (mathematically exact vs dense reference: p is 0 elsewhere)
    expert_kernel<<<dim3(NB / 64, NE), 256, EXPERT_SMEM>>>(x, bias, W1, b1, W2, b2, yout);
}

// round 2
// speedup vs baseline: 1.6738x; 1.6738x over previous
#include <cuda_runtime.h>
#include <math.h>

#define NB 65536
#define ND 256
#define NE 16
#define NH 256
#define NO 256
#define NG 1024

// ---------------- scratch (device globals; no allocations allowed) ----------------
__device__ float g_h1[(size_t)NB * NG];   // gate hidden 1
__device__ float g_h2[(size_t)NB * ND];   // gate hidden 2
__device__ int   g_e0[NB], g_e1[NB];
__device__ float g_w0[NB], g_w1[NB];
__device__ int   g_counts[NE], g_offsets[NE], g_cursor[NE];
__device__ int   g_ptok[2 * NB];
__device__ float g_pw[2 * NB];

__global__ void zero_counts_kernel() {
    if (threadIdx.x < NE) g_counts[threadIdx.x] = 0;
}

// ---------------- tf32 mma helpers ----------------
__device__ __forceinline__ unsigned f2tf(float v) {
    unsigned r;
    asm("cvt.rna.tf32.f32 %0, %1;" : "=r"(r) : "f"(v));
    return r;
}

__device__ __forceinline__ void mma_tf32(float c[4], const unsigned a[4], const unsigned b[2]) {
    asm volatile(
        "mma.sync.aligned.m16n8k8.row.col.f32.tf32.tf32.f32 "
        "{%0,%1,%2,%3},{%4,%5,%6,%7},{%8,%9},{%0,%1,%2,%3};"
        : "+f"(c[0]), "+f"(c[1]), "+f"(c[2]), "+f"(c[3])
        : "r"(a[0]), "r"(a[1]), "r"(a[2]), "r"(a[3]), "r"(b[0]), "r"(b[1]));
}

// ---------------- gate GEMM: C = relu(A @ B + bias), tf32x3 (~fp32 accuracy) --------
// BM=128 BN=128 BK=16, 256 threads (8 warps, 2m x 4n), warp tile 64x32.
#define ALD 20     // A smem ld (16 + 4 pad): frag banks (20g+c)%32 all distinct
#define BLD 136    // B smem ld (128 + 8 pad): frag banks (8c+g)%32 all distinct

template<bool RELU>
__global__ __launch_bounds__(256, 2) void gemm_tf32x3(
    const float* __restrict__ A, const float* __restrict__ Bm,
    const float* __restrict__ bias, float* __restrict__ C,
    int M, int N, int K) {
    __shared__ float As[2][128 * ALD];
    __shared__ float Bs[2][16 * BLD];
    const int tid = threadIdx.x;
    const int lane = tid & 31;
    const int g = lane >> 2, cq = lane & 3;
    const int warp = tid >> 5;
    const int wm = (warp & 1) * 64;
    const int wn = (warp >> 1) * 32;
    const size_t bm = (size_t)blockIdx.y * 128;
    const int bn = blockIdx.x * 128;

    float acc[4][4][4];
#pragma unroll
    for (int mt = 0; mt < 4; mt++)
#pragma unroll
        for (int nt = 0; nt < 4; nt++)
#pragma unroll
            for (int i = 0; i < 4; i++) acc[mt][nt][i] = 0.f;

    float4 pa[2], pb[2];

    auto ldg = [&](int kt) {
#pragma unroll
        for (int i = 0; i < 2; i++) {
            int idx = tid * 2 + i;
            pa[i] = *(const float4*)(A + (bm + (idx >> 2)) * (size_t)K + kt * 16 + (idx & 3) * 4);
        }
#pragma unroll
        for (int i = 0; i < 2; i++) {
            int idx = tid * 2 + i;
            pb[i] = *(const float4*)(Bm + (size_t)(kt * 16 + (idx >> 5)) * N + bn + (idx & 31) * 4);
        }
    };
    auto sts = [&](int buf) {
#pragma unroll
        for (int i = 0; i < 2; i++) {
            int idx = tid * 2 + i;
            *(float4*)&As[buf][(idx >> 2) * ALD + (idx & 3) * 4] = pa[i];
        }
#pragma unroll
        for (int i = 0; i < 2; i++) {
            int idx = tid * 2 + i;
            *(float4*)&Bs[buf][(idx >> 5) * BLD + (idx & 31) * 4] = pb[i];
        }
    };

    ldg(0);
    sts(0);
    __syncthreads();

    const int nk = K / 16;
    for (int kt = 0; kt < nk; kt++) {
        const int buf = kt & 1;
        if (kt + 1 < nk) ldg(kt + 1);
#pragma unroll
        for (int ks = 0; ks < 2; ks++) {
            const int kk = ks * 8;
            unsigned bhi[4][2], blo[4][2];
#pragma unroll
            for (int nt = 0; nt < 4; nt++)
#pragma unroll
                for (int i = 0; i < 2; i++) {
                    float v = Bs[buf][(kk + cq + i * 4) * BLD + wn + nt * 8 + g];
                    bhi[nt][i] = f2tf(v);
                    blo[nt][i] = f2tf(v - __uint_as_float(bhi[nt][i]));
                }
#pragma unroll
            for (int mt = 0; mt < 4; mt++) {
                unsigned ahi[4], alo[4];
#pragma unroll
                for (int i = 0; i < 4; i++) {
                    float v = As[buf][(wm + mt * 16 + g + (i & 1) * 8) * ALD + kk + cq + (i >> 1) * 4];
                    ahi[i] = f2tf(v);
                    alo[i] = f2tf(v - __uint_as_float(ahi[i]));
                }
#pragma unroll
                for (int nt = 0; nt < 4; nt++) {
                    mma_tf32(acc[mt][nt], alo, bhi[nt]);
                    mma_tf32(acc[mt][nt], ahi, blo[nt]);
                    mma_tf32(acc[mt][nt], ahi, bhi[nt]);
                }
            }
        }
        if (kt + 1 < nk) sts(buf ^ 1);
        __syncthreads();
    }

    // epilogue
#pragma unroll
    for (int mt = 0; mt < 4; mt++) {
#pragma unroll
        for (int nt = 0; nt < 4; nt++) {
            const size_t r0 = bm + wm + mt * 16 + g;
            const int cn = bn + wn + nt * 8 + cq * 2;
            float b0 = bias[cn], b1 = bias[cn + 1];
            float v0 = acc[mt][nt][0] + b0, v1 = acc[mt][nt][1] + b1;
            float v2 = acc[mt][nt][2] + b0, v3 = acc[mt][nt][3] + b1;
            if (RELU) {
                v0 = fmaxf(v0, 0.f); v1 = fmaxf(v1, 0.f);
                v2 = fmaxf(v2, 0.f); v3 = fmaxf(v3, 0.f);
            }
            *(float2*)(C + r0 * N + cn) = make_float2(v0, v1);
            *(float2*)(C + (r0 + 8) * N + cn) = make_float2(v2, v3);
        }
    }
}

// ---------------- gate head: logits -> softmax -> top2 -> p + routing (fp32) -------
__global__ __launch_bounds__(256) void gate3_kernel(
    const float* __restrict__ h2, const float* __restrict__ g3,
    const float* __restrict__ gb3, float* __restrict__ p_out) {
    __shared__ float sg3t[16][260];
    __shared__ float sh2[8][256];
    const int tid = threadIdx.x;
    const int warp = tid >> 5, lane = tid & 31;

    for (int idx = tid; idx < ND * NE; idx += 256)
        sg3t[idx & 15][idx >> 4] = g3[idx];

    const int t = blockIdx.x * 8 + warp;
    const float4* hrow = (const float4*)(h2 + (size_t)t * ND);
    for (int i = lane; i < ND / 4; i += 32)
        *(float4*)&sh2[warp][i * 4] = hrow[i];
    __syncthreads();

    float logit = -1e30f;
    if (lane < 16) {
        float s = gb3[lane];
#pragma unroll 8
        for (int k4 = 0; k4 < ND / 4; k4++) {
            float4 hv = *(const float4*)&sh2[warp][k4 * 4];
            float4 gv = *(const float4*)&sg3t[lane][k4 * 4];
            s += hv.x * gv.x + hv.y * gv.y + hv.z * gv.z + hv.w * gv.w;
        }
        logit = s;
    }
    float mx = logit;
#pragma unroll
    for (int m = 8; m >= 1; m >>= 1)
        mx = fmaxf(mx, __shfl_xor_sync(0xffffffffu, mx, m, 16));
    float ex = expf(logit - mx);
    float sum = ex;
#pragma unroll
    for (int m = 8; m >= 1; m >>= 1)
        sum += __shfl_xor_sync(0xffffffffu, sum, m, 16);
    float pv = ex / sum;

    float v1 = pv; int i1 = lane & 15;
#pragma unroll
    for (int m = 8; m >= 1; m >>= 1) {
        float ov = __shfl_xor_sync(0xffffffffu, v1, m, 16);
        int   oi = __shfl_xor_sync(0xffffffffu, i1, m, 16);
        if (ov > v1 || (ov == v1 && oi < i1)) { v1 = ov; i1 = oi; }
    }
    float c2 = ((lane & 15) == i1) ? -1.f : pv;
    float v2 = c2; int i2 = lane & 15;
#pragma unroll
    for (int m = 8; m >= 1; m >>= 1) {
        float ov = __shfl_xor_sync(0xffffffffu, v2, m, 16);
        int   oi = __shfl_xor_sync(0xffffffffu, i2, m, 16);
        if (ov > v2 || (ov == v2 && oi < i2)) { v2 = ov; i2 = oi; }
    }
    float inv = 1.f / (v1 + v2 + 1e-9f);
    if (lane < 16) {
        float po = 0.f;
        if (lane == i1) po = v1 * inv;
        else if (lane == i2) po = v2 * inv;
        p_out[(size_t)t * NE + lane] = po;
    }
    if (lane == 0) {
        g_e0[t] = i1; g_e1[t] = i2;
        g_w0[t] = v1 * inv; g_w1[t] = v2 * inv;
        atomicAdd(&g_counts[i1], 1);
        atomicAdd(&g_counts[i2], 1);
    }
}

__global__ void scan_kernel() {
    if (threadIdx.x == 0) {
        int off = 0;
#pragma unroll
        for (int e = 0; e < NE; e++) {
            g_offsets[e] = off;
            g_cursor[e] = off;
            off += g_counts[e];
        }
    }
}

__global__ __launch_bounds__(256) void scatter_kernel() {
    int t = blockIdx.x * 256 + threadIdx.x;
    int e0 = g_e0[t], e1 = g_e1[t];
    int p0 = atomicAdd(&g_cursor[e0], 1);
    g_ptok[p0] = t; g_pw[p0] = g_w0[t];
    int p1 = atomicAdd(&g_cursor[e1], 1);
    g_ptok[p1] = t; g_pw[p1] = g_w1[t];
}

// ---------------- expert kernel: 64-token tile, tf32 mma, fused 2 GEMMs ------------
#define XLD 260    // x/he smem ld: frag banks (4g+c)%32 distinct
#define WLD 264    // W smem ld: frag banks (8c+g)%32 distinct
#define EXP_SMEM ((2 * 64 * XLD + 2 * 16 * WLD) * 4)   // 166912 B

// one 64x256 @ 256x256 tf32 GEMM; sa [64][XLD] raw fp32; W [256][256] row-major
__device__ __forceinline__ void expert_mm(
    const float* __restrict__ sa, float* __restrict__ sw,
    const float* __restrict__ W, float acc[4][4][4],
    int tid, int g, int cq, int wn) {
    float4 pw[4];
    auto ldw = [&](int kt) {
#pragma unroll
        for (int i = 0; i < 4; i++) {
            int idx = tid + i * 256;
            pw[i] = *(const float4*)(W + (size_t)(kt * 16 + (idx >> 6)) * 256 + (idx & 63) * 4);
        }
    };
    auto stw = [&](int buf) {
#pragma unroll
        for (int i = 0; i < 4; i++) {
            int idx = tid + i * 256;
            *(float4*)&sw[buf * 16 * WLD + (idx >> 6) * WLD + (idx & 63) * 4] = pw[i];
        }
    };
    ldw(0);
    stw(0);
    __syncthreads();
    for (int kt = 0; kt < 16; kt++) {
        const int buf = kt & 1;
        if (kt + 1 < 16) ldw(kt + 1);
#pragma unroll
        for (int ks = 0; ks < 2; ks++) {
            const int kw = ks * 8;
            const int kk = kt * 16 + kw;
            unsigned bf[4][2];
#pragma unroll
            for (int nt = 0; nt < 4; nt++)
#pragma unroll
                for (int i = 0; i < 2; i++)
                    bf[nt][i] = f2tf(sw[buf * 16 * WLD + (kw + cq + i * 4) * WLD + wn + nt * 8 + g]);
#pragma unroll
            for (int mt = 0; mt < 4; mt++) {
                unsigned af[4];
#pragma unroll
                for (int i = 0; i < 4; i++)
                    af[i] = f2tf(sa[(mt * 16 + g + (i & 1) * 8) * XLD + kk + cq + (i >> 1) * 4]);
#pragma unroll
                for (int nt = 0; nt < 4; nt++)
                    mma_tf32(acc[mt][nt], af, bf[nt]);
            }
        }
        if (kt + 1 < 16) stw(buf ^ 1);
        __syncthreads();
    }
}

__global__ __launch_bounds__(256) void expert_kernel(
    const float* __restrict__ x, const float* __restrict__ bias,
    const float* __restrict__ W1, const float* __restrict__ b1,
    const float* __restrict__ W2, const float* __restrict__ b2,
    float* __restrict__ y) {
    const int e = blockIdx.y;
    const int cnt = g_counts[e];
    const int start = blockIdx.x * 64;
    if (start >= cnt) return;
    const int base = g_offsets[e];
    const int valid = min(64, cnt - start);

    extern __shared__ float sm[];
    float* s_xb = sm;
    float* s_he = sm + 64 * XLD;
    float* s_w  = sm + 2 * 64 * XLD;
    __shared__ int   s_tok[64];
    __shared__ float s_gw[64];

    const int tid = threadIdx.x, lane = tid & 31;
    const int g = lane >> 2, cq = lane & 3;
    const int wn = (tid >> 5) * 32;

    if (tid < 64) {
        int tok = 0; float w = 0.f;
        if (tid < valid) { tok = g_ptok[base + start + tid]; w = g_pw[base + start + tid]; }
        s_tok[tid] = tok; s_gw[tid] = w;
    }
    __syncthreads();

    // gather xb = x[tok] + bias[e]
#pragma unroll
    for (int i = 0; i < 16; i++) {
        int idx = tid + i * 256;
        int row = idx >> 6;
        int c4 = (idx & 63) * 4;
        float4 xv = *(const float4*)(x + (size_t)s_tok[row] * ND + c4);
        float4 bv = *(const float4*)(bias + (size_t)e * ND + c4);
        *(float4*)&s_xb[row * XLD + c4] =
            make_float4(xv.x + bv.x, xv.y + bv.y, xv.z + bv.z, xv.w + bv.w);
    }
    __syncthreads();

    float acc[4][4][4];
#pragma unroll
    for (int mt = 0; mt < 4; mt++)
#pragma unroll
        for (int nt = 0; nt < 4; nt++)
#pragma unroll
            for (int i = 0; i < 4; i++) acc[mt][nt][i] = 0.f;

    // GEMM1: he = relu(xb @ W1[e] + b1[e])
    expert_mm(s_xb, s_w, W1 + (size_t)e * ND * NH, acc, tid, g, cq, wn);
#pragma unroll
    for (int mt = 0; mt < 4; mt++) {
#pragma unroll
        for (int nt = 0; nt < 4; nt++) {
            int r = mt * 16 + g;
            int c = wn + nt * 8 + cq * 2;
            float bb0 = b1[(size_t)e * NH + c];
            float bb1 = b1[(size_t)e * NH + c + 1];
            s_he[r * XLD + c]           = fmaxf(acc[mt][nt][0] + bb0, 0.f);
            s_he[r * XLD + c + 1]       = fmaxf(acc[mt][nt][1] + bb1, 0.f);
            s_he[(r + 8) * XLD + c]     = fmaxf(acc[mt][nt][2] + bb0, 0.f);
            s_he[(r + 8) * XLD + c + 1] = fmaxf(acc[mt][nt][3] + bb1, 0.f);
        }
    }
    __syncthreads();

#pragma unroll
    for (int mt = 0; mt < 4; mt++)
#pragma unroll
        for (int nt = 0; nt < 4; nt++)
#pragma unroll
            for (int i = 0; i < 4; i++) acc[mt][nt][i] = 0.f;

    // GEMM2: out = (he @ W2[e] + b2[e]) * gate_w -> atomicAdd into y
    expert_mm(s_he, s_w, W2 + (size_t)e * NH * NO, acc, tid, g, cq, wn);
#pragma unroll
    for (int mt = 0; mt < 4; mt++) {
#pragma unroll
        for (int nt = 0; nt < 4; nt++) {
            int r = mt * 16 + g;
            int c = wn + nt * 8 + cq * 2;
            float bb0 = b2[(size_t)e * NO + c];
            float bb1 = b2[(size_t)e * NO + c + 1];
            if (r < valid) {
                float gw = s_gw[r];
                float* yb = y + (size_t)s_tok[r] * NO + c;
                atomicAdd(yb,     (acc[mt][nt][0] + bb0) * gw);
                atomicAdd(yb + 1, (acc[mt][nt][1] + bb1) * gw);
            }
            int r2 = r + 8;
            if (r2 < valid) {
                float gw = s_gw[r2];
                float* yb = y + (size_t)s_tok[r2] * NO + c;
                atomicAdd(yb,     (acc[mt][nt][2] + bb0) * gw);
                atomicAdd(yb + 1, (acc[mt][nt][3] + bb1) * gw);
            }
        }
    }
}

// ---------------- launch ----------------
extern "C" void kernel_launch(void* const* d_in, const int* in_sizes, int n_in,
                              void* d_out, int out_size) {
    const float* x    = (const float*)d_in[0];
    const float* bias = (const float*)d_in[1];
    const float* W1   = (const float*)d_in[2];
    const float* b1   = (const float*)d_in[3];
    const float* W2   = (const float*)d_in[4];
    const float* b2   = (const float*)d_in[5];
    const float* g1   = (const float*)d_in[6];
    const float* gb1  = (const float*)d_in[7];
    const float* g2   = (const float*)d_in[8];
    const float* gb2  = (const float*)d_in[9];
    const float* g3   = (const float*)d_in[10];
    const float* gb3  = (const float*)d_in[11];

    float* yout = (float*)d_out;            // [B, O]
    float* pout = yout + (size_t)NB * NO;   // [B, E]

    float *h1p = nullptr, *h2p = nullptr;
    cudaGetSymbolAddress((void**)&h1p, g_h1);
    cudaGetSymbolAddress((void**)&h2p, g_h2);
    cudaFuncSetAttribute(expert_kernel,
                         cudaFuncAttributeMaxDynamicSharedMemorySize, EXP_SMEM);

    cudaMemsetAsync(yout, 0, (size_t)NB * NO * sizeof(float), 0);
    zero_counts_kernel<<<1, 32>>>();

    // gate MLP (tf32x3 ~= fp32 accuracy)
    gemm_tf32x3<true><<<dim3(NG / 128, NB / 128), 256>>>(x,   g1, gb1, h1p, NB, NG, ND);
    gemm_tf32x3<true><<<dim3(ND / 128, NB / 128), 256>>>(h1p, g2, gb2, h2p, NB, ND, NG);
    gate3_kernel<<<NB / 8, 256>>>(h2p, g3, gb3, pout);

    // routing
    scan_kernel<<<1, 32>>>();
    scatter_kernel<<<NB / 256, 256>>>();

    // top-2 expert compute (exact vs dense reference: p is 0 outside top-2)
    expert_kernel<<<dim3(NB / 64, NE), 256, EXP_SMEM>>>(x, bias, W1, b1, W2, b2, yout);
}

// round 5
// speedup vs baseline: 1.8852x; 1.1263x over previous
#include <cuda_runtime.h>
#include <cuda_fp16.h>
#include <cstdint>
#include <stdint.h>
#include <math.h>

#define NB 65536
#define ND 256
#define NE 16
#define NH 256
#define NO 256
#define NG 1024

// ---------------- scratch (device globals; no allocations allowed) ----------------
__device__ __half g_xh[(size_t)NB * ND], g_xl[(size_t)NB * ND];
__device__ __half g_h1h[(size_t)NB * NG], g_h1l[(size_t)NB * NG];
__device__ float  g_h2[(size_t)NB * ND];
__device__ __half g_B1h[NG * ND], g_B1l[NG * ND];   // [1024][256] K-major (transposed g1)
__device__ __half g_B2h[ND * NG], g_B2l[ND * NG];   // [256][1024] K-major (transposed g2)
__device__ int   g_e0[NB], g_e1[NB];
__device__ float g_w0[NB], g_w1[NB];
__device__ int   g_counts[NE], g_offsets[NE], g_cursor[NE];
__device__ int   g_ptok[2 * NB];
__device__ float g_pw[2 * NB];

__global__ void zero_counts_kernel() {
    if (threadIdx.x < NE) g_counts[threadIdx.x] = 0;
}

// ---------------- fp16 helpers ----------------
__device__ __forceinline__ uint32_t packh(__half a, __half b) {
    return ((uint32_t)__half_as_ushort(b) << 16) | (uint32_t)__half_as_ushort(a);
}
__device__ __forceinline__ void split2(float v, __half& h, __half& l) {
    h = __float2half_rn(v);
    l = __float2half_rn(v - __half2float(h));
}
__device__ __forceinline__ void mma_f16(float c[4], const uint32_t a[4], const uint32_t b[2]) {
    asm volatile(
        "mma.sync.aligned.m16n8k16.row.col.f32.f16.f16.f32 "
        "{%0,%1,%2,%3},{%4,%5,%6,%7},{%8,%9},{%0,%1,%2,%3};"
        : "+f"(c[0]), "+f"(c[1]), "+f"(c[2]), "+f"(c[3])
        : "r"(a[0]), "r"(a[1]), "r"(a[2]), "r"(a[3]), "r"(b[0]), "r"(b[1]));
}

// ---------------- prep kernels ----------------
__global__ __launch_bounds__(256) void split_x_kernel(const float* __restrict__ x) {
    size_t i = (size_t)blockIdx.x * 256 + threadIdx.x;   // per float4
    float4 v = ((const float4*)x)[i];
    __half h[4], l[4];
    split2(v.x, h[0], l[0]); split2(v.y, h[1], l[1]);
    split2(v.z, h[2], l[2]); split2(v.w, h[3], l[3]);
    ((uint2*)g_xh)[i] = make_uint2(packh(h[0], h[1]), packh(h[2], h[3]));
    ((uint2*)g_xl)[i] = make_uint2(packh(l[0], l[1]), packh(l[2], l[3]));
}

// out[n*K+k] = split(W[k*N+n])
__global__ __launch_bounds__(256) void prep_w_kernel(
    const float* __restrict__ W, __half* __restrict__ oh, __half* __restrict__ ol,
    int K, int N) {
    int idx = blockIdx.x * 256 + threadIdx.x;
    int n = idx / K, k = idx - n * K;
    float v = W[(size_t)k * N + n];
    __half h, l;
    split2(v, h, l);
    oh[idx] = h; ol[idx] = l;
}

// ---------------- gate GEMM: C = relu(A@B^T + bias), fp16 3-product (~tf32x3) -------
// A planes [M][K] fp16, B planes [N][K] fp16 (K-major). BM=128 BN=128 BK=32.
// 8 warps (2m x 4n), warp tile 64x32. Smem u32-packed fp16 pairs, LD=20 conflict-free.
#define ALD 20

template<int K, int OUTW, bool SPLIT_OUT>
__global__ __launch_bounds__(256, 2) void gate_fp16(
    const __half* __restrict__ Ah_, const __half* __restrict__ Al_,
    const __half* __restrict__ Bh_, const __half* __restrict__ Bl_,
    const float* __restrict__ bias,
    uint32_t* __restrict__ Oh32, uint32_t* __restrict__ Ol32,
    float* __restrict__ Of) {
    __shared__ uint32_t SAh[128][ALD], SAl[128][ALD], SBh[128][ALD], SBl[128][ALD];
    const int tid = threadIdx.x, lane = tid & 31, warp = tid >> 5;
    const int g = lane >> 2, cq = lane & 3;
    const int wm = (warp & 1) * 64, wn = (warp >> 1) * 32;
    const size_t bm = (size_t)blockIdx.y * 128;
    const size_t bn = (size_t)blockIdx.x * 128;

    float acc[4][4][4];
#pragma unroll
    for (int mt = 0; mt < 4; mt++)
#pragma unroll
        for (int nt = 0; nt < 4; nt++)
#pragma unroll
            for (int i = 0; i < 4; i++) acc[mt][nt][i] = 0.f;

    const int NCH = K / 32;
    for (int kt = 0; kt < NCH; kt++) {
        __syncthreads();   // previous chunk's mma reads done
#pragma unroll
        for (int i = 0; i < 2; i++) {
            const int idx = tid * 2 + i;
            const int row = idx >> 2;
            const int q = (idx & 3) * 8;           // half offset within 32-chunk
            const size_t ao = (bm + row) * (size_t)K + kt * 32 + q;
            const size_t bo = (bn + row) * (size_t)K + kt * 32 + q;
            const int sc = (idx & 3) * 4;          // u32 col in smem
            *(uint4*)&SAh[row][sc] = *(const uint4*)(Ah_ + ao);
            *(uint4*)&SAl[row][sc] = *(const uint4*)(Al_ + ao);
            *(uint4*)&SBh[row][sc] = *(const uint4*)(Bh_ + bo);
            *(uint4*)&SBl[row][sc] = *(const uint4*)(Bl_ + bo);
        }
        __syncthreads();
#pragma unroll
        for (int s = 0; s < 2; s++) {
            const int ks = s * 8;
            uint32_t bh[4][2], bl[4][2];
#pragma unroll
            for (int nt = 0; nt < 4; nt++) {
                const int n = wn + nt * 8 + g;
                bh[nt][0] = SBh[n][ks + cq];
                bh[nt][1] = SBh[n][ks + cq + 4];
                bl[nt][0] = SBl[n][ks + cq];
                bl[nt][1] = SBl[n][ks + cq + 4];
            }
#pragma unroll
            for (int mt = 0; mt < 4; mt++) {
                const int r0 = wm + mt * 16 + g;
                uint32_t ah[4], al[4];
                ah[0] = SAh[r0][ks + cq];     ah[1] = SAh[r0 + 8][ks + cq];
                ah[2] = SAh[r0][ks + cq + 4]; ah[3] = SAh[r0 + 8][ks + cq + 4];
                al[0] = SAl[r0][ks + cq];     al[1] = SAl[r0 + 8][ks + cq];
                al[2] = SAl[r0][ks + cq + 4]; al[3] = SAl[r0 + 8][ks + cq + 4];
#pragma unroll
                for (int nt = 0; nt < 4; nt++) {
                    mma_f16(acc[mt][nt], al, bh[nt]);   // l*h
                    mma_f16(acc[mt][nt], ah, bl[nt]);   // h*l
                    mma_f16(acc[mt][nt], ah, bh[nt]);   // h*h
                }
            }
        }
    }

    // epilogue
#pragma unroll
    for (int mt = 0; mt < 4; mt++) {
#pragma unroll
        for (int nt = 0; nt < 4; nt++) {
            const size_t r0 = bm + wm + mt * 16 + g;
            const int c = (int)bn + wn + nt * 8 + cq * 2;
            const float b0 = __ldg(&bias[c]), b1 = __ldg(&bias[c + 1]);
            float v0 = fmaxf(acc[mt][nt][0] + b0, 0.f);
            float v1 = fmaxf(acc[mt][nt][1] + b1, 0.f);
            float v2 = fmaxf(acc[mt][nt][2] + b0, 0.f);
            float v3 = fmaxf(acc[mt][nt][3] + b1, 0.f);
            if (SPLIT_OUT) {
                __half h0, l0, h1, l1, h2, l2, h3, l3;
                split2(v0, h0, l0); split2(v1, h1, l1);
                split2(v2, h2, l2); split2(v3, h3, l3);
                Oh32[r0 * (OUTW / 2) + (c >> 1)]       = packh(h0, h1);
                Ol32[r0 * (OUTW / 2) + (c >> 1)]       = packh(l0, l1);
                Oh32[(r0 + 8) * (OUTW / 2) + (c >> 1)] = packh(h2, h3);
                Ol32[(r0 + 8) * (OUTW / 2) + (c >> 1)] = packh(l2, l3);
            } else {
                *(float2*)(Of + r0 * OUTW + c)       = make_float2(v0, v1);
                *(float2*)(Of + (r0 + 8) * OUTW + c) = make_float2(v2, v3);
            }
        }
    }
}

// ---------------- tf32 mma helpers (expert path, proven) ----------------
__device__ __forceinline__ unsigned f2tf(float v) {
    unsigned r;
    asm("cvt.rna.tf32.f32 %0, %1;" : "=r"(r) : "f"(v));
    return r;
}
__device__ __forceinline__ void mma_tf32(float c[4], const unsigned a[4], const unsigned b[2]) {
    asm volatile(
        "mma.sync.aligned.m16n8k8.row.col.f32.tf32.tf32.f32 "
        "{%0,%1,%2,%3},{%4,%5,%6,%7},{%8,%9},{%0,%1,%2,%3};"
        : "+f"(c[0]), "+f"(c[1]), "+f"(c[2]), "+f"(c[3])
        : "r"(a[0]), "r"(a[1]), "r"(a[2]), "r"(a[3]), "r"(b[0]), "r"(b[1]));
}

// ---------------- gate head: logits -> softmax -> top2 -> p + routing (fp32) -------
__global__ __launch_bounds__(256) void gate3_kernel(
    const float* __restrict__ h2, const float* __restrict__ g3,
    const float* __restrict__ gb3, float* __restrict__ p_out) {
    __shared__ float sg3t[16][260];
    __shared__ float sh2[8][256];
    const int tid = threadIdx.x;
    const int warp = tid >> 5, lane = tid & 31;

    for (int idx = tid; idx < ND * NE; idx += 256)
        sg3t[idx & 15][idx >> 4] = g3[idx];

    const int t = blockIdx.x * 8 + warp;
    const float4* hrow = (const float4*)(h2 + (size_t)t * ND);
    for (int i = lane; i < ND / 4; i += 32)
        *(float4*)&sh2[warp][i * 4] = hrow[i];
    __syncthreads();

    // all 32 lanes: expert = lane&15, K-half = lane>>4
    const int e = lane & 15, half = lane >> 4;
    const float* hp = &sh2[warp][half * 128];
    const float* gp = &sg3t[e][half * 128];
    float s = 0.f;
#pragma unroll 8
    for (int k4 = 0; k4 < 32; k4++) {
        float4 hv = *(const float4*)(hp + k4 * 4);
        float4 gv = *(const float4*)(gp + k4 * 4);
        s += hv.x * gv.x + hv.y * gv.y + hv.z * gv.z + hv.w * gv.w;
    }
    s += __shfl_xor_sync(0xffffffffu, s, 16);
    float logit = (lane < 16) ? s + gb3[e] : -1e30f;

    float mx = logit;
#pragma unroll
    for (int m = 8; m >= 1; m >>= 1)
        mx = fmaxf(mx, __shfl_xor_sync(0xffffffffu, mx, m, 16));
    float ex = expf(logit - mx);
    float sum = ex;
#pragma unroll
    for (int m = 8; m >= 1; m >>= 1)
        sum += __shfl_xor_sync(0xffffffffu, sum, m, 16);
    float pv = ex / sum;

    float v1 = pv; int i1 = e;
#pragma unroll
    for (int m = 8; m >= 1; m >>= 1) {
        float ov = __shfl_xor_sync(0xffffffffu, v1, m, 16);
        int   oi = __shfl_xor_sync(0xffffffffu, i1, m, 16);
        if (ov > v1 || (ov == v1 && oi < i1)) { v1 = ov; i1 = oi; }
    }
    float c2 = (e == i1) ? -1.f : pv;
    float v2 = c2; int i2 = e;
#pragma unroll
    for (int m = 8; m >= 1; m >>= 1) {
        float ov = __shfl_xor_sync(0xffffffffu, v2, m, 16);
        int   oi = __shfl_xor_sync(0xffffffffu, i2, m, 16);
        if (ov > v2 || (ov == v2 && oi < i2)) { v2 = ov; i2 = oi; }
    }
    float inv = 1.f / (v1 + v2 + 1e-9f);
    if (lane < 16) {
        float po = 0.f;
        if (e == i1) po = v1 * inv;
        else if (e == i2) po = v2 * inv;
        p_out[(size_t)t * NE + e] = po;
    }
    if (lane == 0) {
        g_e0[t] = i1; g_e1[t] = i2;
        g_w0[t] = v1 * inv; g_w1[t] = v2 * inv;
        atomicAdd(&g_counts[i1], 1);
        atomicAdd(&g_counts[i2], 1);
    }
}

__global__ void scan_kernel() {
    if (threadIdx.x == 0) {
        int off = 0;
#pragma unroll
        for (int e = 0; e < NE; e++) {
            g_offsets[e] = off;
            g_cursor[e] = off;
            off += g_counts[e];
        }
    }
}

__global__ __launch_bounds__(256) void scatter_kernel() {
    int t = blockIdx.x * 256 + threadIdx.x;
    int e0 = g_e0[t], e1 = g_e1[t];
    int p0 = atomicAdd(&g_cursor[e0], 1);
    g_ptok[p0] = t; g_pw[p0] = g_w0[t];
    int p1 = atomicAdd(&g_cursor[e1], 1);
    g_ptok[p1] = t; g_pw[p1] = g_w1[t];
}

// ---------------- expert kernel: 64-token tile, tf32 mma, fused 2 GEMMs ------------
#define XLD 260
#define WLD 264
#define EXP_SMEM ((2 * 64 * XLD + 2 * 16 * WLD) * 4)

__device__ __forceinline__ void expert_mm(
    const float* __restrict__ sa, float* __restrict__ sw,
    const float* __restrict__ W, float acc[4][4][4],
    int tid, int g, int cq, int wn) {
    float4 pw[4];
    auto ldw = [&](int kt) {
#pragma unroll
        for (int i = 0; i < 4; i++) {
            int idx = tid + i * 256;
            pw[i] = *(const float4*)(W + (size_t)(kt * 16 + (idx >> 6)) * 256 + (idx & 63) * 4);
        }
    };
    auto stw = [&](int buf) {
#pragma unroll
        for (int i = 0; i < 4; i++) {
            int idx = tid + i * 256;
            *(float4*)&sw[buf * 16 * WLD + (idx >> 6) * WLD + (idx & 63) * 4] = pw[i];
        }
    };
    ldw(0);
    stw(0);
    __syncthreads();
    for (int kt = 0; kt < 16; kt++) {
        const int buf = kt & 1;
        if (kt + 1 < 16) ldw(kt + 1);
#pragma unroll
        for (int ks = 0; ks < 2; ks++) {
            const int kw = ks * 8;
            const int kk = kt * 16 + kw;
            unsigned bf[4][2];
#pragma unroll
            for (int nt = 0; nt < 4; nt++)
#pragma unroll
                for (int i = 0; i < 2; i++)
                    bf[nt][i] = f2tf(sw[buf * 16 * WLD + (kw + cq + i * 4) * WLD + wn + nt * 8 + g]);
#pragma unroll
            for (int mt = 0; mt < 4; mt++) {
                unsigned af[4];
#pragma unroll
                for (int i = 0; i < 4; i++)
                    af[i] = f2tf(sa[(mt * 16 + g + (i & 1) * 8) * XLD + kk + cq + (i >> 1) * 4]);
#pragma unroll
                for (int nt = 0; nt < 4; nt++)
                    mma_tf32(acc[mt][nt], af, bf[nt]);
            }
        }
        if (kt + 1 < 16) stw(buf ^ 1);
        __syncthreads();
    }
}

__global__ __launch_bounds__(256) void expert_kernel(
    const float* __restrict__ x, const float* __restrict__ bias,
    const float* __restrict__ W1, const float* __restrict__ b1,
    const float* __restrict__ W2, const float* __restrict__ b2,
    float* __restrict__ y) {
    const int e = blockIdx.y;
    const int cnt = g_counts[e];
    const int start = blockIdx.x * 64;
    if (start >= cnt) return;
    const int base = g_offsets[e];
    const int valid = min(64, cnt - start);

    extern __shared__ float sm[];
    float* s_xb = sm;
    float* s_he = sm + 64 * XLD;
    float* s_w  = sm + 2 * 64 * XLD;
    __shared__ int   s_tok[64];
    __shared__ float s_gw[64];

    const int tid = threadIdx.x, lane = tid & 31;
    const int g = lane >> 2, cq = lane & 3;
    const int wn = (tid >> 5) * 32;

    if (tid < 64) {
        int tok = 0; float w = 0.f;
        if (tid < valid) { tok = g_ptok[base + start + tid]; w = g_pw[base + start + tid]; }
        s_tok[tid] = tok; s_gw[tid] = w;
    }
    __syncthreads();

#pragma unroll
    for (int i = 0; i < 16; i++) {
        int idx = tid + i * 256;
        int row = idx >> 6;
        int c4 = (idx & 63) * 4;
        float4 xv = *(const float4*)(x + (size_t)s_tok[row] * ND + c4);
        float4 bv = *(const float4*)(bias + (size_t)e * ND + c4);
        *(float4*)&s_xb[row * XLD + c4] =
            make_float4(xv.x + bv.x, xv.y + bv.y, xv.z + bv.z, xv.w + bv.w);
    }
    __syncthreads();

    float acc[4][4][4];
#pragma unroll
    for (int mt = 0; mt < 4; mt++)
#pragma unroll
        for (int nt = 0; nt < 4; nt++)
#pragma unroll
            for (int i = 0; i < 4; i++) acc[mt][nt][i] = 0.f;

    expert_mm(s_xb, s_w, W1 + (size_t)e * ND * NH, acc, tid, g, cq, wn);
#pragma unroll
    for (int mt = 0; mt < 4; mt++) {
#pragma unroll
        for (int nt = 0; nt < 4; nt++) {
            int r = mt * 16 + g;
            int c = wn + nt * 8 + cq * 2;
            float bb0 = b1[(size_t)e * NH + c];
            float bb1 = b1[(size_t)e * NH + c + 1];
            s_he[r * XLD + c]           = fmaxf(acc[mt][nt][0] + bb0, 0.f);
            s_he[r * XLD + c + 1]       = fmaxf(acc[mt][nt][1] + bb1, 0.f);
            s_he[(r + 8) * XLD + c]     = fmaxf(acc[mt][nt][2] + bb0, 0.f);
            s_he[(r + 8) * XLD + c + 1] = fmaxf(acc[mt][nt][3] + bb1, 0.f);
        }
    }
    __syncthreads();

#pragma unroll
    for (int mt = 0; mt < 4; mt++)
#pragma unroll
        for (int nt = 0; nt < 4; nt++)
#pragma unroll
            for (int i = 0; i < 4; i++) acc[mt][nt][i] = 0.f;

    expert_mm(s_he, s_w, W2 + (size_t)e * NH * NO, acc, tid, g, cq, wn);
#pragma unroll
    for (int mt = 0; mt < 4; mt++) {
#pragma unroll
        for (int nt = 0; nt < 4; nt++) {
            int r = mt * 16 + g;
            int c = wn + nt * 8 + cq * 2;
            float bb0 = b2[(size_t)e * NO + c];
            float bb1 = b2[(size_t)e * NO + c + 1];
            if (r < valid) {
                float gw = s_gw[r];
                float* yb = y + (size_t)s_tok[r] * NO + c;
                atomicAdd(yb,     (acc[mt][nt][0] + bb0) * gw);
                atomicAdd(yb + 1, (acc[mt][nt][1] + bb1) * gw);
            }
            int r2 = r + 8;
            if (r2 < valid) {
                float gw = s_gw[r2];
                float* yb = y + (size_t)s_tok[r2] * NO + c;
                atomicAdd(yb,     (acc[mt][nt][2] + bb0) * gw);
                atomicAdd(yb + 1, (acc[mt][nt][3] + bb1) * gw);
            }
        }
    }
}

// ---------------- launch ----------------
extern "C" void kernel_launch(void* const* d_in, const int* in_sizes, int n_in,
                              void* d_out, int out_size) {
    const float* x    = (const float*)d_in[0];
    const float* bias = (const float*)d_in[1];
    const float* W1   = (const float*)d_in[2];
    const float* b1   = (const float*)d_in[3];
    const float* W2   = (const float*)d_in[4];
    const float* b2   = (const float*)d_in[5];
    const float* g1   = (const float*)d_in[6];
    const float* gb1  = (const float*)d_in[7];
    const float* g2   = (const float*)d_in[8];
    const float* gb2  = (const float*)d_in[9];
    const float* g3   = (const float*)d_in[10];
    const float* gb3  = (const float*)d_in[11];

    float* yout = (float*)d_out;
    float* pout = yout + (size_t)NB * NO;

    __half *xh, *xl, *h1h, *h1l, *B1h, *B1l, *B2h, *B2l;
    float* h2p;
    cudaGetSymbolAddress((void**)&xh, g_xh);   cudaGetSymbolAddress((void**)&xl, g_xl);
    cudaGetSymbolAddress((void**)&h1h, g_h1h); cudaGetSymbolAddress((void**)&h1l, g_h1l);
    cudaGetSymbolAddress((void**)&B1h, g_B1h); cudaGetSymbolAddress((void**)&B1l, g_B1l);
    cudaGetSymbolAddress((void**)&B2h, g_B2h); cudaGetSymbolAddress((void**)&B2l, g_B2l);
    cudaGetSymbolAddress((void**)&h2p, g_h2);

    cudaFuncSetAttribute(expert_kernel,
                         cudaFuncAttributeMaxDynamicSharedMemorySize, EXP_SMEM);

    cudaMemsetAsync(yout, 0, (size_t)NB * NO * sizeof(float), 0);
    zero_counts_kernel<<<1, 32>>>();

    // prep: split x; transpose+split gate weights into fp16 planes
    split_x_kernel<<<NB * ND / 4 / 256, 256>>>(x);
    prep_w_kernel<<<NG * ND / 256, 256>>>(g1, B1h, B1l, ND, NG);
    prep_w_kernel<<<NG * ND / 256, 256>>>(g2, B2h, B2l, NG, ND);

    // gate MLP: fp16 3-product mma.sync (same precision structure as tf32x3, 2x rate)
    gate_fp16<ND, NG, true><<<dim3(NG / 128, NB / 128), 256>>>(
        xh, xl, B1h, B1l, gb1, (uint32_t*)h1h, (uint32_t*)h1l, nullptr);
    gate_fp16<NG, ND, false><<<dim3(ND / 128, NB / 128), 256>>>(
        h1h, h1l, B2h, B2l, gb2, nullptr, nullptr, h2p);
    gate3_kernel<<<NB / 8, 256>>>(h2p, g3, gb3, pout);

    // routing
    scan_kernel<<<1, 32>>>();
    scatter_kernel<<<NB / 256, 256>>>();

    // top-2 expert compute (exact vs dense reference: p is 0 outside top-2)
    expert_kernel<<<dim3(NB / 64, NE), 256, EXP_SMEM>>>(x, bias, W1, b1, W2, b2, yout);
}

// round 8
// speedup vs baseline: 2.2818x; 1.2103x over previous
#include <cuda_runtime.h>
#include <cuda_fp16.h>
#include <cstdint>
#include <stdint.h>
#include <math.h>

#define NB 65536
#define ND 256
#define NE 16
#define NH 256
#define NO 256
#define NG 1024

// ---------------- scratch (device globals; no allocations allowed) ----------------
__device__ __align__(16) __half g_xh[(size_t)NB * ND], g_xl[(size_t)NB * ND];
__device__ __align__(16) __half g_h1h[(size_t)NB * NG], g_h1l[(size_t)NB * NG];
__device__ float  g_h2[(size_t)NB * ND];
__device__ __align__(16) __half g_B1h[NG * ND], g_B1l[NG * ND];   // [1024][256] K-major
__device__ __align__(16) __half g_B2h[ND * NG], g_B2l[ND * NG];   // [256][1024] K-major
__device__ __align__(16) __half g_W1T[NE * NH * ND];  // [e][h][d] K-major fp16
__device__ __align__(16) __half g_W2T[NE * NO * NH];  // [e][o][h] K-major fp16
__device__ int   g_e0[NB], g_e1[NB];
__device__ float g_w0[NB], g_w1[NB];
__device__ int   g_counts[NE], g_offsets[NE], g_cursor[NE];
__device__ int   g_ptok[2 * NB];
__device__ float g_pw[2 * NB];

__global__ void zero_counts_kernel() {
    if (threadIdx.x < NE) g_counts[threadIdx.x] = 0;
}

// ---------------- fp16 helpers ----------------
__device__ __forceinline__ uint32_t packh(__half a, __half b) {
    return ((uint32_t)__half_as_ushort(b) << 16) | (uint32_t)__half_as_ushort(a);
}
__device__ __forceinline__ void split2(float v, __half& h, __half& l) {
    h = __float2half_rn(v);
    l = __float2half_rn(v - __half2float(h));
}
__device__ __forceinline__ void mma_f16(float c[4], const uint32_t a[4], const uint32_t b[2]) {
    asm volatile(
        "mma.sync.aligned.m16n8k16.row.col.f32.f16.f16.f32 "
        "{%0,%1,%2,%3},{%4,%5,%6,%7},{%8,%9},{%0,%1,%2,%3};"
        : "+f"(c[0]), "+f"(c[1]), "+f"(c[2]), "+f"(c[3])
        : "r"(a[0]), "r"(a[1]), "r"(a[2]), "r"(a[3]), "r"(b[0]), "r"(b[1]));
}

// ---------------- prep kernels ----------------
__global__ __launch_bounds__(256) void split_x_kernel(const float* __restrict__ x) {
    size_t i = (size_t)blockIdx.x * 256 + threadIdx.x;   // per float4
    float4 v = ((const float4*)x)[i];
    __half h[4], l[4];
    split2(v.x, h[0], l[0]); split2(v.y, h[1], l[1]);
    split2(v.z, h[2], l[2]); split2(v.w, h[3], l[3]);
    ((uint2*)g_xh)[i] = make_uint2(packh(h[0], h[1]), packh(h[2], h[3]));
    ((uint2*)g_xl)[i] = make_uint2(packh(l[0], l[1]), packh(l[2], l[3]));
}

// out[n*K+k] = split(W[k*N+n])   (gate weights, 2-plane split)
__global__ __launch_bounds__(256) void prep_w_kernel(
    const float* __restrict__ W, __half* __restrict__ oh, __half* __restrict__ ol,
    int K, int N) {
    int idx = blockIdx.x * 256 + threadIdx.x;
    int n = idx / K, k = idx - n * K;
    float v = W[(size_t)k * N + n];
    __half h, l;
    split2(v, h, l);
    oh[idx] = h; ol[idx] = l;
}

// expert weights: WT[e][n][k] = (half) W[e][k][n],  K=N=256
__global__ __launch_bounds__(256) void prep_ew_kernel(
    const float* __restrict__ W, __half* __restrict__ WT) {
    int idx = blockIdx.x * 256 + threadIdx.x;      // e*65536 + k*256 + n
    int e = idx >> 16, rem = idx & 65535;
    int k = rem >> 8, n = rem & 255;
    WT[(size_t)e * 65536 + n * 256 + k] = __float2half_rn(W[idx]);
}

// ---------------- gate GEMM: C = relu(A@B^T + bias), fp16 3-product -----------------
// A planes [M][K], B planes [N][K] fp16 K-major. BM=128 BN=128 BK=32.
// Double-buffered smem (4 planes x [128][20] words), register prefetch, 1 sync/iter.
#define GSEG (128 * 20)
#define GATE_SMEM (2 * 4 * GSEG * 4)   // 81920 B

template<int K, int OUTW, bool SPLIT_OUT>
__global__ __launch_bounds__(256, 2) void gate_fp16(
    const __half* __restrict__ Ah_, const __half* __restrict__ Al_,
    const __half* __restrict__ Bh_, const __half* __restrict__ Bl_,
    const float* __restrict__ bias,
    uint32_t* __restrict__ Oh32, uint32_t* __restrict__ Ol32,
    float* __restrict__ Of) {
    extern __shared__ uint32_t gsm[];
    const int tid = threadIdx.x, lane = tid & 31, warp = tid >> 5;
    const int g = lane >> 2, cq = lane & 3;
    const int wm = (warp & 1) * 64, wn = (warp >> 1) * 32;
    const size_t bm = (size_t)blockIdx.y * 128;
    const size_t bn = (size_t)blockIdx.x * 128;

    float acc[4][4][4];
#pragma unroll
    for (int mt = 0; mt < 4; mt++)
#pragma unroll
        for (int nt = 0; nt < 4; nt++)
#pragma unroll
            for (int i = 0; i < 4; i++) acc[mt][nt][i] = 0.f;

    uint4 pAh[2], pAl[2], pBh[2], pBl[2];
    auto ldg = [&](int kt) {
#pragma unroll
        for (int i = 0; i < 2; i++) {
            const int idx = tid * 2 + i;
            const int row = idx >> 2;
            const int q = (idx & 3) * 8;   // halves
            const size_t ao = (bm + row) * (size_t)K + kt * 32 + q;
            const size_t bo = (bn + row) * (size_t)K + kt * 32 + q;
            pAh[i] = *(const uint4*)(Ah_ + ao);
            pAl[i] = *(const uint4*)(Al_ + ao);
            pBh[i] = *(const uint4*)(Bh_ + bo);
            pBl[i] = *(const uint4*)(Bl_ + bo);
        }
    };
    auto sts = [&](int buf) {
        uint32_t* base = gsm + buf * 4 * GSEG;
#pragma unroll
        for (int i = 0; i < 2; i++) {
            const int idx = tid * 2 + i;
            const int off = (idx >> 2) * 20 + (idx & 3) * 4;
            *(uint4*)&base[0 * GSEG + off] = pAh[i];
            *(uint4*)&base[1 * GSEG + off] = pAl[i];
            *(uint4*)&base[2 * GSEG + off] = pBh[i];
            *(uint4*)&base[3 * GSEG + off] = pBl[i];
        }
    };

    ldg(0); sts(0);
    __syncthreads();

    const int NCH = K / 32;
    for (int kt = 0; kt < NCH; kt++) {
        if (kt + 1 < NCH) ldg(kt + 1);
        const uint32_t* SAh = gsm + (kt & 1) * 4 * GSEG;
        const uint32_t* SAl = SAh + GSEG;
        const uint32_t* SBh = SAh + 2 * GSEG;
        const uint32_t* SBl = SAh + 3 * GSEG;
#pragma unroll
        for (int s = 0; s < 2; s++) {
            const int ks = s * 8;   // word offset in 20-word row
            uint32_t bh[4][2], bl[4][2];
#pragma unroll
            for (int nt = 0; nt < 4; nt++) {
                const int n = wn + nt * 8 + g;
                bh[nt][0] = SBh[n * 20 + ks + cq];
                bh[nt][1] = SBh[n * 20 + ks + cq + 4];
                bl[nt][0] = SBl[n * 20 + ks + cq];
                bl[nt][1] = SBl[n * 20 + ks + cq + 4];
            }
#pragma unroll
            for (int mt = 0; mt < 4; mt++) {
                const int r0 = wm + mt * 16 + g;
                uint32_t ah[4], al[4];
                ah[0] = SAh[r0 * 20 + ks + cq];       ah[1] = SAh[(r0 + 8) * 20 + ks + cq];
                ah[2] = SAh[r0 * 20 + ks + cq + 4];   ah[3] = SAh[(r0 + 8) * 20 + ks + cq + 4];
                al[0] = SAl[r0 * 20 + ks + cq];       al[1] = SAl[(r0 + 8) * 20 + ks + cq];
                al[2] = SAl[r0 * 20 + ks + cq + 4];   al[3] = SAl[(r0 + 8) * 20 + ks + cq + 4];
#pragma unroll
                for (int nt = 0; nt < 4; nt++) {
                    mma_f16(acc[mt][nt], al, bh[nt]);   // l*h
                    mma_f16(acc[mt][nt], ah, bl[nt]);   // h*l
                    mma_f16(acc[mt][nt], ah, bh[nt]);   // h*h
                }
            }
        }
        if (kt + 1 < NCH) sts((kt + 1) & 1);
        __syncthreads();
    }

    // epilogue
#pragma unroll
    for (int mt = 0; mt < 4; mt++) {
#pragma unroll
        for (int nt = 0; nt < 4; nt++) {
            const size_t r0 = bm + wm + mt * 16 + g;
            const int c = (int)bn + wn + nt * 8 + cq * 2;
            const float b0 = __ldg(&bias[c]), b1 = __ldg(&bias[c + 1]);
            float v0 = fmaxf(acc[mt][nt][0] + b0, 0.f);
            float v1 = fmaxf(acc[mt][nt][1] + b1, 0.f);
            float v2 = fmaxf(acc[mt][nt][2] + b0, 0.f);
            float v3 = fmaxf(acc[mt][nt][3] + b1, 0.f);
            if (SPLIT_OUT) {
                __half h0, l0, h1, l1, h2, l2, h3, l3;
                split2(v0, h0, l0); split2(v1, h1, l1);
                split2(v2, h2, l2); split2(v3, h3, l3);
                Oh32[r0 * (OUTW / 2) + (c >> 1)]       = packh(h0, h1);
                Ol32[r0 * (OUTW / 2) + (c >> 1)]       = packh(l0, l1);
                Oh32[(r0 + 8) * (OUTW / 2) + (c >> 1)] = packh(h2, h3);
                Ol32[(r0 + 8) * (OUTW / 2) + (c >> 1)] = packh(l2, l3);
            } else {
                *(float2*)(Of + r0 * OUTW + c)       = make_float2(v0, v1);
                *(float2*)(Of + (r0 + 8) * OUTW + c) = make_float2(v2, v3);
            }
        }
    }
}

// ---------------- gate head: logits -> softmax -> top2 -> p + routing (fp32) -------
__global__ __launch_bounds__(256) void gate3_kernel(
    const float* __restrict__ h2, const float* __restrict__ g3,
    const float* __restrict__ gb3, float* __restrict__ p_out) {
    __shared__ float sg3t[16][260];
    __shared__ float sh2[8][256];
    const int tid = threadIdx.x;
    const int warp = tid >> 5, lane = tid & 31;

    for (int idx = tid; idx < ND * NE; idx += 256)
        sg3t[idx & 15][idx >> 4] = g3[idx];

    const int t = blockIdx.x * 8 + warp;
    const float4* hrow = (const float4*)(h2 + (size_t)t * ND);
    for (int i = lane; i < ND / 4; i += 32)
        *(float4*)&sh2[warp][i * 4] = hrow[i];
    __syncthreads();

    const int e = lane & 15, half = lane >> 4;
    const float* hp = &sh2[warp][half * 128];
    const float* gp = &sg3t[e][half * 128];
    float s = 0.f;
#pragma unroll 8
    for (int k4 = 0; k4 < 32; k4++) {
        float4 hv = *(const float4*)(hp + k4 * 4);
        float4 gv = *(const float4*)(gp + k4 * 4);
        s += hv.x * gv.x + hv.y * gv.y + hv.z * gv.z + hv.w * gv.w;
    }
    s += __shfl_xor_sync(0xffffffffu, s, 16);
    float logit = (lane < 16) ? s + gb3[e] : -1e30f;

    float mx = logit;
#pragma unroll
    for (int m = 8; m >= 1; m >>= 1)
        mx = fmaxf(mx, __shfl_xor_sync(0xffffffffu, mx, m, 16));
    float ex = expf(logit - mx);
    float sum = ex;
#pragma unroll
    for (int m = 8; m >= 1; m >>= 1)
        sum += __shfl_xor_sync(0xffffffffu, sum, m, 16);
    float pv = ex / sum;

    float v1 = pv; int i1 = e;
#pragma unroll
    for (int m = 8; m >= 1; m >>= 1) {
        float ov = __shfl_xor_sync(0xffffffffu, v1, m, 16);
        int   oi = __shfl_xor_sync(0xffffffffu, i1, m, 16);
        if (ov > v1 || (ov == v1 && oi < i1)) { v1 = ov; i1 = oi; }
    }
    float c2 = (e == i1) ? -1.f : pv;
    float v2 = c2; int i2 = e;
#pragma unroll
    for (int m = 8; m >= 1; m >>= 1) {
        float ov = __shfl_xor_sync(0xffffffffu, v2, m, 16);
        int   oi = __shfl_xor_sync(0xffffffffu, i2, m, 16);
        if (ov > v2 || (ov == v2 && oi < i2)) { v2 = ov; i2 = oi; }
    }
    float inv = 1.f / (v1 + v2 + 1e-9f);
    if (lane < 16) {
        float po = 0.f;
        if (e == i1) po = v1 * inv;
        else if (e == i2) po = v2 * inv;
        p_out[(size_t)t * NE + e] = po;
    }
    if (lane == 0) {
        g_e0[t] = i1; g_e1[t] = i2;
        g_w0[t] = v1 * inv; g_w1[t] = v2 * inv;
        atomicAdd(&g_counts[i1], 1);
        atomicAdd(&g_counts[i2], 1);
    }
}

__global__ void scan_kernel() {
    if (threadIdx.x == 0) {
        int off = 0;
#pragma unroll
        for (int e = 0; e < NE; e++) {
            g_offsets[e] = off;
            g_cursor[e] = off;
            off += g_counts[e];
        }
    }
}

__global__ __launch_bounds__(256) void scatter_kernel() {
    int t = blockIdx.x * 256 + threadIdx.x;
    int e0 = g_e0[t], e1 = g_e1[t];
    int p0 = atomicAdd(&g_cursor[e0], 1);
    g_ptok[p0] = t; g_pw[p0] = g_w0[t];
    int p1 = atomicAdd(&g_cursor[e1], 1);
    g_ptok[p1] = t; g_pw[p1] = g_w1[t];
}

// ---------------- expert kernel: 64-token tile, fp16 mma, fused 2 GEMMs ------------
// activations fp16 smem [64][264]; weights pre-transposed fp16 [e][n][k];
// W tile smem [256][20 words], double-buffered.
#define XLDH 264                    // halves per act row (word stride 132)
#define EWRD 20                     // words per W row
#define EXP_SMEM (2 * 64 * XLDH * 2 + 2 * 256 * EWRD * 4)   // 108544 B

__device__ __forceinline__ void expert_mm16(
    const uint32_t* __restrict__ sa, uint32_t* __restrict__ sw,
    const __half* __restrict__ WT, float acc[4][4][4],
    int tid, int g, int cq, int wn) {
    uint4 pw[4];
    // one chunk = 256 rows x 32 halves = 1024 uint4 -> 4 per thread
    auto ldw = [&](int kc) {
#pragma unroll
        for (int i = 0; i < 4; i++) {
            const int idx = tid + i * 256;
            const int n = idx >> 2;
            const int q = (idx & 3) * 8;
            pw[i] = *(const uint4*)(WT + n * 256 + kc * 32 + q);
        }
    };
    auto stw = [&](int buf) {
#pragma unroll
        for (int i = 0; i < 4; i++) {
            const int idx = tid + i * 256;
            *(uint4*)&sw[buf * 256 * EWRD + (idx >> 2) * EWRD + (idx & 3) * 4] = pw[i];
        }
    };
    ldw(0); stw(0);
    __syncthreads();
    for (int kc = 0; kc < 8; kc++) {
        if (kc + 1 < 8) ldw(kc + 1);
        const uint32_t* W_s = sw + (kc & 1) * 256 * EWRD;
#pragma unroll
        for (int s = 0; s < 2; s++) {
            const int ks = s * 8;                 // word offset in W row
            const int ka = kc * 16 + s * 8;       // word offset in act row
            uint32_t bf[4][2];
#pragma unroll
            for (int nt = 0; nt < 4; nt++) {
                const int n = wn + nt * 8 + g;
                bf[nt][0] = W_s[n * EWRD + ks + cq];
                bf[nt][1] = W_s[n * EWRD + ks + cq + 4];
            }
#pragma unroll
            for (int mt = 0; mt < 4; mt++) {
                const int r0 = mt * 16 + g;
                uint32_t af[4];
                af[0] = sa[r0 * 132 + ka + cq];
                af[1] = sa[(r0 + 8) * 132 + ka + cq];
                af[2] = sa[r0 * 132 + ka + cq + 4];
                af[3] = sa[(r0 + 8) * 132 + ka + cq + 4];
#pragma unroll
                for (int nt = 0; nt < 4; nt++)
                    mma_f16(acc[mt][nt], af, bf[nt]);
            }
        }
        if (kc + 1 < 8) stw((kc + 1) & 1);
        __syncthreads();
    }
}

__global__ __launch_bounds__(256) void expert_kernel(
    const float* __restrict__ x, const float* __restrict__ bias,
    const __half* __restrict__ W1T, const float* __restrict__ b1,
    const __half* __restrict__ W2T, const float* __restrict__ b2,
    float* __restrict__ y) {
    const int e = blockIdx.y;
    const int cnt = g_counts[e];
    const int start = blockIdx.x * 64;
    if (start >= cnt) return;
    const int base = g_offsets[e];
    const int valid = min(64, cnt - start);

    extern __shared__ char esm[];
    __half* s_xb = (__half*)esm;                        // [64][264]
    __half* s_he = s_xb + 64 * XLDH;                    // [64][264]
    uint32_t* s_w = (uint32_t*)(s_he + 64 * XLDH);      // 2 x [256][20]
    __shared__ int   s_tok[64];
    __shared__ float s_gw[64];

    const int tid = threadIdx.x, lane = tid & 31;
    const int g = lane >> 2, cq = lane & 3;
    const int wn = (tid >> 5) * 32;

    if (tid < 64) {
        int tok = 0; float w = 0.f;
        if (tid < valid) { tok = g_ptok[base + start + tid]; w = g_pw[base + start + tid]; }
        s_tok[tid] = tok; s_gw[tid] = w;
    }
    __syncthreads();

    // gather xb = half(x[tok] + bias[e])
#pragma unroll
    for (int i = 0; i < 16; i++) {
        int idx = tid + i * 256;
        int row = idx >> 6;
        int c4 = (idx & 63) * 4;
        float4 xv = *(const float4*)(x + (size_t)s_tok[row] * ND + c4);
        float4 bv = *(const float4*)(bias + (size_t)e * ND + c4);
        uint32_t p0 = packh(__float2half_rn(xv.x + bv.x), __float2half_rn(xv.y + bv.y));
        uint32_t p1 = packh(__float2half_rn(xv.z + bv.z), __float2half_rn(xv.w + bv.w));
        *(uint2*)(s_xb + row * XLDH + c4) = make_uint2(p0, p1);
    }
    __syncthreads();

    float acc[4][4][4];
#pragma unroll
    for (int mt = 0; mt < 4; mt++)
#pragma unroll
        for (int nt = 0; nt < 4; nt++)
#pragma unroll
            for (int i = 0; i < 4; i++) acc[mt][nt][i] = 0.f;

    // GEMM1: he = relu(xb @ W1[e] + b1[e])
    expert_mm16((const uint32_t*)s_xb, s_w, W1T + (size_t)e * ND * NH, acc, tid, g, cq, wn);
#pragma unroll
    for (int mt = 0; mt < 4; mt++) {
#pragma unroll
        for (int nt = 0; nt < 4; nt++) {
            int r = mt * 16 + g;
            int c = wn + nt * 8 + cq * 2;
            float bb0 = b1[(size_t)e * NH + c];
            float bb1 = b1[(size_t)e * NH + c + 1];
            float v0 = fmaxf(acc[mt][nt][0] + bb0, 0.f);
            float v1 = fmaxf(acc[mt][nt][1] + bb1, 0.f);
            float v2 = fmaxf(acc[mt][nt][2] + bb0, 0.f);
            float v3 = fmaxf(acc[mt][nt][3] + bb1, 0.f);
            *(uint32_t*)(s_he + r * XLDH + c) =
                packh(__float2half_rn(v0), __float2half_rn(v1));
            *(uint32_t*)(s_he + (r + 8) * XLDH + c) =
                packh(__float2half_rn(v2), __float2half_rn(v3));
        }
    }
    __syncthreads();

#pragma unroll
    for (int mt = 0; mt < 4; mt++)
#pragma unroll
        for (int nt = 0; nt < 4; nt++)
#pragma unroll
            for (int i = 0; i < 4; i++) acc[mt][nt][i] = 0.f;

    // GEMM2: out = (he @ W2[e] + b2[e]) * gate_w -> atomicAdd into y
    expert_mm16((const uint32_t*)s_he, s_w, W2T + (size_t)e * NH * NO, acc, tid, g, cq, wn);
#pragma unroll
    for (int mt = 0; mt < 4; mt++) {
#pragma unroll
        for (int nt = 0; nt < 4; nt++) {
            int r = mt * 16 + g;
            int c = wn + nt * 8 + cq * 2;
            float bb0 = b2[(size_t)e * NO + c];
            float bb1 = b2[(size_t)e * NO + c + 1];
            if (r < valid) {
                float gw = s_gw[r];
                float* yb = y + (size_t)s_tok[r] * NO + c;
                atomicAdd(yb,     (acc[mt][nt][0] + bb0) * gw);
                atomicAdd(yb + 1, (acc[mt][nt][1] + bb1) * gw);
            }
            int r2 = r + 8;
            if (r2 < valid) {
                float gw = s_gw[r2];
                float* yb = y + (size_t)s_tok[r2] * NO + c;
                atomicAdd(yb,     (acc[mt][nt][2] + bb0) * gw);
                atomicAdd(yb + 1, (acc[mt][nt][3] + bb1) * gw);
            }
        }
    }
}

// ---------------- launch ----------------
extern "C" void kernel_launch(void* const* d_in, const int* in_sizes, int n_in,
                              void* d_out, int out_size) {
    const float* x    = (const float*)d_in[0];
    const float* bias = (const float*)d_in[1];
    const float* W1   = (const float*)d_in[2];
    const float* b1   = (const float*)d_in[3];
    const float* W2   = (const float*)d_in[4];
    const float* b2   = (const float*)d_in[5];
    const float* g1   = (const float*)d_in[6];
    const float* gb1  = (const float*)d_in[7];
    const float* g2   = (const float*)d_in[8];
    const float* gb2  = (const float*)d_in[9];
    const float* g3   = (const float*)d_in[10];
    const float* gb3  = (const float*)d_in[11];

    float* yout = (float*)d_out;
    float* pout = yout + (size_t)NB * NO;

    __half *xh, *xl, *h1h, *h1l, *B1h, *B1l, *B2h, *B2l, *W1T, *W2T;
    float* h2p;
    cudaGetSymbolAddress((void**)&xh, g_xh);   cudaGetSymbolAddress((void**)&xl, g_xl);
    cudaGetSymbolAddress((void**)&h1h, g_h1h); cudaGetSymbolAddress((void**)&h1l, g_h1l);
    cudaGetSymbolAddress((void**)&B1h, g_B1h); cudaGetSymbolAddress((void**)&B1l, g_B1l);
    cudaGetSymbolAddress((void**)&B2h, g_B2h); cudaGetSymbolAddress((void**)&B2l, g_B2l);
    cudaGetSymbolAddress((void**)&W1T, g_W1T); cudaGetSymbolAddress((void**)&W2T, g_W2T);
    cudaGetSymbolAddress((void**)&h2p, g_h2);

    cudaFuncSetAttribute(gate_fp16<ND, NG, true>,
                         cudaFuncAttributeMaxDynamicSharedMemorySize, GATE_SMEM);
    cudaFuncSetAttribute(gate_fp16<NG, ND, false>,
                         cudaFuncAttributeMaxDynamicSharedMemorySize, GATE_SMEM);
    cudaFuncSetAttribute(expert_kernel,
                         cudaFuncAttributeMaxDynamicSharedMemorySize, EXP_SMEM);

    cudaMemsetAsync(yout, 0, (size_t)NB * NO * sizeof(float), 0);
    zero_counts_kernel<<<1, 32>>>();

    // prep: split x; transpose+split gate weights; transpose+convert expert weights
    split_x_kernel<<<NB * ND / 4 / 256, 256>>>(x);
    prep_w_kernel<<<NG * ND / 256, 256>>>(g1, B1h, B1l, ND, NG);
    prep_w_kernel<<<NG * ND / 256, 256>>>(g2, B2h, B2l, NG, ND);
    prep_ew_kernel<<<NE * NH * ND / 256, 256>>>(W1, W1T);
    prep_ew_kernel<<<NE * NO * NH / 256, 256>>>(W2, W2T);

    // gate MLP: fp16 3-product mma.sync (tf32x3-equivalent precision)
    gate_fp16<ND, NG, true><<<dim3(NG / 128, NB / 128), 256, GATE_SMEM>>>(
        xh, xl, B1h, B1l, gb1, (uint32_t*)h1h, (uint32_t*)h1l, nullptr);
    gate_fp16<NG, ND, false><<<dim3(ND / 128, NB / 128), 256, GATE_SMEM>>>(
        h1h, h1l, B2h, B2l, gb2, nullptr, nullptr, h2p);
    gate3_kernel<<<NB / 8, 256>>>(h2p, g3, gb3, pout);

    // routing
    scan_kernel<<<1, 32>>>();
    scatter_kernel<<<NB / 256, 256>>>();

    // top-2 expert compute (exact vs dense reference: p is 0 outside top-2)
    expert_kernel<<<dim3(NB / 64, NE), 256, EXP_SMEM>>>(
        x, bias, W1T, b1, W2T, b2, yout);
}

// round 9
// speedup vs baseline: 2.2844x; 1.0011x over previous
#include <cuda_runtime.h>
#include <cuda_fp16.h>
#include <cstdint>
#include <stdint.h>
#include <math.h>

#define NB 65536
#define ND 256
#define NE 16
#define NH 256
#define NO 256
#define NG 1024

// ---------------- scratch (device globals; no allocations allowed) ----------------
__device__ __align__(16) __half g_xh[(size_t)NB * ND], g_xl[(size_t)NB * ND];
__device__ __align__(16) __half g_h1h[(size_t)NB * NG], g_h1l[(size_t)NB * NG];
__device__ float  g_h2[(size_t)NB * ND];
__device__ __align__(16) __half g_B1h[NG * ND], g_B1l[NG * ND];   // [1024][256] K-major
__device__ __align__(16) __half g_B2h[ND * NG], g_B2l[ND * NG];   // [256][1024] K-major
__device__ __align__(16) __half g_W1T[NE * NH * ND];  // [e][h][d] K-major fp16
__device__ __align__(16) __half g_W2T[NE * NO * NH];  // [e][o][h] K-major fp16
__device__ int   g_e0[NB], g_e1[NB];
__device__ float g_w0[NB], g_w1[NB];
__device__ int   g_counts[NE], g_offsets[NE], g_cursor[NE];
__device__ int   g_ptok[2 * NB];
__device__ float g_pw[2 * NB];

__global__ void zero_counts_kernel() {
    if (threadIdx.x < NE) g_counts[threadIdx.x] = 0;
}

// ---------------- fp16 helpers ----------------
__device__ __forceinline__ uint32_t packh(__half a, __half b) {
    return ((uint32_t)__half_as_ushort(b) << 16) | (uint32_t)__half_as_ushort(a);
}
__device__ __forceinline__ void split2(float v, __half& h, __half& l) {
    h = __float2half_rn(v);
    l = __float2half_rn(v - __half2float(h));
}
__device__ __forceinline__ void mma_f16(float c[4], const uint32_t a[4], const uint32_t b[2]) {
    asm volatile(
        "mma.sync.aligned.m16n8k16.row.col.f32.f16.f16.f32 "
        "{%0,%1,%2,%3},{%4,%5,%6,%7},{%8,%9},{%0,%1,%2,%3};"
        : "+f"(c[0]), "+f"(c[1]), "+f"(c[2]), "+f"(c[3])
        : "r"(a[0]), "r"(a[1]), "r"(a[2]), "r"(a[3]), "r"(b[0]), "r"(b[1]));
}

// ---------------- prep kernels ----------------
__global__ __launch_bounds__(256) void split_x_kernel(const float* __restrict__ x) {
    size_t i = (size_t)blockIdx.x * 256 + threadIdx.x;   // per float4
    float4 v = ((const float4*)x)[i];
    __half h[4], l[4];
    split2(v.x, h[0], l[0]); split2(v.y, h[1], l[1]);
    split2(v.z, h[2], l[2]); split2(v.w, h[3], l[3]);
    ((uint2*)g_xh)[i] = make_uint2(packh(h[0], h[1]), packh(h[2], h[3]));
    ((uint2*)g_xl)[i] = make_uint2(packh(l[0], l[1]), packh(l[2], l[3]));
}

// out[n*K+k] = split(W[k*N+n])   (gate weights, 2-plane split)
__global__ __launch_bounds__(256) void prep_w_kernel(
    const float* __restrict__ W, __half* __restrict__ oh, __half* __restrict__ ol,
    int K, int N) {
    int idx = blockIdx.x * 256 + threadIdx.x;
    int n = idx / K, k = idx - n * K;
    float v = W[(size_t)k * N + n];
    __half h, l;
    split2(v, h, l);
    oh[idx] = h; ol[idx] = l;
}

// expert weights: WT[e][n][k] = (half) W[e][k][n],  K=N=256
__global__ __launch_bounds__(256) void prep_ew_kernel(
    const float* __restrict__ W, __half* __restrict__ WT) {
    int idx = blockIdx.x * 256 + threadIdx.x;      // e*65536 + k*256 + n
    int e = idx >> 16, rem = idx & 65535;
    int k = rem >> 8, n = rem & 255;
    WT[(size_t)e * 65536 + n * 256 + k] = __float2half_rn(W[idx]);
}

// ---------------- gate GEMM: C = relu(A@B^T + bias), fp16 3-product -----------------
// A planes [M][K], B planes [N][K] fp16 K-major. BM=128 BN=128 BK=32.
// Double-buffered smem (4 planes x [128][20] words), register prefetch, 1 sync/iter.
#define GSEG (128 * 20)
#define GATE_SMEM (2 * 4 * GSEG * 4)   // 81920 B

template<int K, int OUTW, bool SPLIT_OUT>
__global__ __launch_bounds__(256, 2) void gate_fp16(
    const __half* __restrict__ Ah_, const __half* __restrict__ Al_,
    const __half* __restrict__ Bh_, const __half* __restrict__ Bl_,
    const float* __restrict__ bias,
    uint32_t* __restrict__ Oh32, uint32_t* __restrict__ Ol32,
    float* __restrict__ Of) {
    extern __shared__ uint32_t gsm[];
    const int tid = threadIdx.x, lane = tid & 31, warp = tid >> 5;
    const int g = lane >> 2, cq = lane & 3;
    const int wm = (warp & 1) * 64, wn = (warp >> 1) * 32;
    const size_t bm = (size_t)blockIdx.y * 128;
    const size_t bn = (size_t)blockIdx.x * 128;

    float acc[4][4][4];
#pragma unroll
    for (int mt = 0; mt < 4; mt++)
#pragma unroll
        for (int nt = 0; nt < 4; nt++)
#pragma unroll
            for (int i = 0; i < 4; i++) acc[mt][nt][i] = 0.f;

    uint4 pAh[2], pAl[2], pBh[2], pBl[2];
    auto ldg = [&](int kt) {
#pragma unroll
        for (int i = 0; i < 2; i++) {
            const int idx = tid * 2 + i;
            const int row = idx >> 2;
            const int q = (idx & 3) * 8;   // halves
            const size_t ao = (bm + row) * (size_t)K + kt * 32 + q;
            const size_t bo = (bn + row) * (size_t)K + kt * 32 + q;
            pAh[i] = *(const uint4*)(Ah_ + ao);
            pAl[i] = *(const uint4*)(Al_ + ao);
            pBh[i] = *(const uint4*)(Bh_ + bo);
            pBl[i] = *(const uint4*)(Bl_ + bo);
        }
    };
    auto sts = [&](int buf) {
        uint32_t* base = gsm + buf * 4 * GSEG;
#pragma unroll
        for (int i = 0; i < 2; i++) {
            const int idx = tid * 2 + i;
            const int off = (idx >> 2) * 20 + (idx & 3) * 4;
            *(uint4*)&base[0 * GSEG + off] = pAh[i];
            *(uint4*)&base[1 * GSEG + off] = pAl[i];
            *(uint4*)&base[2 * GSEG + off] = pBh[i];
            *(uint4*)&base[3 * GSEG + off] = pBl[i];
        }
    };

    ldg(0); sts(0);
    __syncthreads();

    const int NCH = K / 32;
    for (int kt = 0; kt < NCH; kt++) {
        if (kt + 1 < NCH) ldg(kt + 1);
        const uint32_t* SAh = gsm + (kt & 1) * 4 * GSEG;
        const uint32_t* SAl = SAh + GSEG;
        const uint32_t* SBh = SAh + 2 * GSEG;
        const uint32_t* SBl = SAh + 3 * GSEG;
#pragma unroll
        for (int s = 0; s < 2; s++) {
            const int ks = s * 8;   // word offset in 20-word row
            uint32_t bh[4][2], bl[4][2];
#pragma unroll
            for (int nt = 0; nt < 4; nt++) {
                const int n = wn + nt * 8 + g;
                bh[nt][0] = SBh[n * 20 + ks + cq];
                bh[nt][1] = SBh[n * 20 + ks + cq + 4];
                bl[nt][0] = SBl[n * 20 + ks + cq];
                bl[nt][1] = SBl[n * 20 + ks + cq + 4];
            }
#pragma unroll
            for (int mt = 0; mt < 4; mt++) {
                const int r0 = wm + mt * 16 + g;
                uint32_t ah[4], al[4];
                ah[0] = SAh[r0 * 20 + ks + cq];       ah[1] = SAh[(r0 + 8) * 20 + ks + cq];
                ah[2] = SAh[r0 * 20 + ks + cq + 4];   ah[3] = SAh[(r0 + 8) * 20 + ks + cq + 4];
                al[0] = SAl[r0 * 20 + ks + cq];       al[1] = SAl[(r0 + 8) * 20 + ks + cq];
                al[2] = SAl[r0 * 20 + ks + cq + 4];   al[3] = SAl[(r0 + 8) * 20 + ks + cq + 4];
#pragma unroll
                for (int nt = 0; nt < 4; nt++) {
                    mma_f16(acc[mt][nt], al, bh[nt]);   // l*h
                    mma_f16(acc[mt][nt], ah, bl[nt]);   // h*l
                    mma_f16(acc[mt][nt], ah, bh[nt]);   // h*h
                }
            }
        }
        if (kt + 1 < NCH) sts((kt + 1) & 1);
        __syncthreads();
    }

    // epilogue
#pragma unroll
    for (int mt = 0; mt < 4; mt++) {
#pragma unroll
        for (int nt = 0; nt < 4; nt++) {
            const size_t r0 = bm + wm + mt * 16 + g;
            const int c = (int)bn + wn + nt * 8 + cq * 2;
            const float b0 = __ldg(&bias[c]), b1 = __ldg(&bias[c + 1]);
            float v0 = fmaxf(acc[mt][nt][0] + b0, 0.f);
            float v1 = fmaxf(acc[mt][nt][1] + b1, 0.f);
            float v2 = fmaxf(acc[mt][nt][2] + b0, 0.f);
            float v3 = fmaxf(acc[mt][nt][3] + b1, 0.f);
            if (SPLIT_OUT) {
                __half h0, l0, h1, l1, h2, l2, h3, l3;
                split2(v0, h0, l0); split2(v1, h1, l1);
                split2(v2, h2, l2); split2(v3, h3, l3);
                Oh32[r0 * (OUTW / 2) + (c >> 1)]       = packh(h0, h1);
                Ol32[r0 * (OUTW / 2) + (c >> 1)]       = packh(l0, l1);
                Oh32[(r0 + 8) * (OUTW / 2) + (c >> 1)] = packh(h2, h3);
                Ol32[(r0 + 8) * (OUTW / 2) + (c >> 1)] = packh(l2, l3);
            } else {
                *(float2*)(Of + r0 * OUTW + c)       = make_float2(v0, v1);
                *(float2*)(Of + (r0 + 8) * OUTW + c) = make_float2(v2, v3);
            }
        }
    }
}

// ---------------- gate head: logits -> softmax -> top2 -> p + routing (fp32) -------
__global__ __launch_bounds__(256) void gate3_kernel(
    const float* __restrict__ h2, const float* __restrict__ g3,
    const float* __restrict__ gb3, float* __restrict__ p_out) {
    __shared__ float sg3t[16][260];
    __shared__ float sh2[8][256];
    const int tid = threadIdx.x;
    const int warp = tid >> 5, lane = tid & 31;

    for (int idx = tid; idx < ND * NE; idx += 256)
        sg3t[idx & 15][idx >> 4] = g3[idx];

    const int t = blockIdx.x * 8 + warp;
    const float4* hrow = (const float4*)(h2 + (size_t)t * ND);
    for (int i = lane; i < ND / 4; i += 32)
        *(float4*)&sh2[warp][i * 4] = hrow[i];
    __syncthreads();

    const int e = lane & 15, half = lane >> 4;
    const float* hp = &sh2[warp][half * 128];
    const float* gp = &sg3t[e][half * 128];
    float s = 0.f;
#pragma unroll 8
    for (int k4 = 0; k4 < 32; k4++) {
        float4 hv = *(const float4*)(hp + k4 * 4);
        float4 gv = *(const float4*)(gp + k4 * 4);
        s += hv.x * gv.x + hv.y * gv.y + hv.z * gv.z + hv.w * gv.w;
    }
    s += __shfl_xor_sync(0xffffffffu, s, 16);
    float logit = (lane < 16) ? s + gb3[e] : -1e30f;

    float mx = logit;
#pragma unroll
    for (int m = 8; m >= 1; m >>= 1)
        mx = fmaxf(mx, __shfl_xor_sync(0xffffffffu, mx, m, 16));
    float ex = expf(logit - mx);
    float sum = ex;
#pragma unroll
    for (int m = 8; m >= 1; m >>= 1)
        sum += __shfl_xor_sync(0xffffffffu, sum, m, 16);
    float pv = ex / sum;

    float v1 = pv; int i1 = e;
#pragma unroll
    for (int m = 8; m >= 1; m >>= 1) {
        float ov = __shfl_xor_sync(0xffffffffu, v1, m, 16);
        int   oi = __shfl_xor_sync(0xffffffffu, i1, m, 16);
        if (ov > v1 || (ov == v1 && oi < i1)) { v1 = ov; i1 = oi; }
    }
    float c2 = (e == i1) ? -1.f : pv;
    float v2 = c2; int i2 = e;
#pragma unroll
    for (int m = 8; m >= 1; m >>= 1) {
        float ov = __shfl_xor_sync(0xffffffffu, v2, m, 16);
        int   oi = __shfl_xor_sync(0xffffffffu, i2, m, 16);
        if (ov > v2 || (ov == v2 && oi < i2)) { v2 = ov; i2 = oi; }
    }
    float inv = 1.f / (v1 + v2 + 1e-9f);
    if (lane < 16) {
        float po = 0.f;
        if (e == i1) po = v1 * inv;
        else if (e == i2) po = v2 * inv;
        p_out[(size_t)t * NE + e] = po;
    }
    if (lane == 0) {
        g_e0[t] = i1; g_e1[t] = i2;
        g_w0[t] = v1 * inv; g_w1[t] = v2 * inv;
        atomicAdd(&g_counts[i1], 1);
        atomicAdd(&g_counts[i2], 1);
    }
}

__global__ void scan_kernel() {
    if (threadIdx.x == 0) {
        int off = 0;
#pragma unroll
        for (int e = 0; e < NE; e++) {
            g_offsets[e] = off;
            g_cursor[e] = off;
            off += g_counts[e];
        }
    }
}

__global__ __launch_bounds__(256) void scatter_kernel() {
    int t = blockIdx.x * 256 + threadIdx.x;
    int e0 = g_e0[t], e1 = g_e1[t];
    int p0 = atomicAdd(&g_cursor[e0], 1);
    g_ptok[p0] = t; g_pw[p0] = g_w0[t];
    int p1 = atomicAdd(&g_cursor[e1], 1);
    g_ptok[p1] = t; g_pw[p1] = g_w1[t];
}

// ---------------- expert kernel: 64-token tile, fp16 mma, fused 2 GEMMs ------------
// activations fp16 smem [64][264]; weights pre-transposed fp16 [e][n][k];
// W tile smem [256][20 words], double-buffered.
#define XLDH 264                    // halves per act row (word stride 132)
#define EWRD 20                     // words per W row
#define EXP_SMEM (2 * 64 * XLDH * 2 + 2 * 256 * EWRD * 4)   // 108544 B

__device__ __forceinline__ void expert_mm16(
    const uint32_t* __restrict__ sa, uint32_t* __restrict__ sw,
    const __half* __restrict__ WT, float acc[4][4][4],
    int tid, int g, int cq, int wn) {
    uint4 pw[4];
    // one chunk = 256 rows x 32 halves = 1024 uint4 -> 4 per thread
    auto ldw = [&](int kc) {
#pragma unroll
        for (int i = 0; i < 4; i++) {
            const int idx = tid + i * 256;
            const int n = idx >> 2;
            const int q = (idx & 3) * 8;
            pw[i] = *(const uint4*)(WT + n * 256 + kc * 32 + q);
        }
    };
    auto stw = [&](int buf) {
#pragma unroll
        for (int i = 0; i < 4; i++) {
            const int idx = tid + i * 256;
            *(uint4*)&sw[buf * 256 * EWRD + (idx >> 2) * EWRD + (idx & 3) * 4] = pw[i];
        }
    };
    ldw(0); stw(0);
    __syncthreads();
    for (int kc = 0; kc < 8; kc++) {
        if (kc + 1 < 8) ldw(kc + 1);
        const uint32_t* W_s = sw + (kc & 1) * 256 * EWRD;
#pragma unroll
        for (int s = 0; s < 2; s++) {
            const int ks = s * 8;                 // word offset in W row
            const int ka = kc * 16 + s * 8;       // word offset in act row
            uint32_t bf[4][2];
#pragma unroll
            for (int nt = 0; nt < 4; nt++) {
                const int n = wn + nt * 8 + g;
                bf[nt][0] = W_s[n * EWRD + ks + cq];
                bf[nt][1] = W_s[n * EWRD + ks + cq + 4];
            }
#pragma unroll
            for (int mt = 0; mt < 4; mt++) {
                const int r0 = mt * 16 + g;
                uint32_t af[4];
                af[0] = sa[r0 * 132 + ka + cq];
                af[1] = sa[(r0 + 8) * 132 + ka + cq];
                af[2] = sa[r0 * 132 + ka + cq + 4];
                af[3] = sa[(r0 + 8) * 132 + ka + cq + 4];
#pragma unroll
                for (int nt = 0; nt < 4; nt++)
                    mma_f16(acc[mt][nt], af, bf[nt]);
            }
        }
        if (kc + 1 < 8) stw((kc + 1) & 1);
        __syncthreads();
    }
}

__global__ __launch_bounds__(256) void expert_kernel(
    const float* __restrict__ x, const float* __restrict__ bias,
    const __half* __restrict__ W1T, const float* __restrict__ b1,
    const __half* __restrict__ W2T, const float* __restrict__ b2,
    float* __restrict__ y) {
    const int e = blockIdx.y;
    const int cnt = g_counts[e];
    const int start = blockIdx.x * 64;
    if (start >= cnt) return;
    const int base = g_offsets[e];
    const int valid = min(64, cnt - start);

    extern __shared__ char esm[];
    __half* s_xb = (__half*)esm;                        // [64][264]
    __half* s_he = s_xb + 64 * XLDH;                    // [64][264]
    uint32_t* s_w = (uint32_t*)(s_he + 64 * XLDH);      // 2 x [256][20]
    __shared__ int   s_tok[64];
    __shared__ float s_gw[64];

    const int tid = threadIdx.x, lane = tid & 31;
    const int g = lane >> 2, cq = lane & 3;
    const int wn = (tid >> 5) * 32;

    if (tid < 64) {
        int tok = 0; float w = 0.f;
        if (tid < valid) { tok = g_ptok[base + start + tid]; w = g_pw[base + start + tid]; }
        s_tok[tid] = tok; s_gw[tid] = w;
    }
    __syncthreads();

    // gather xb = half(x[tok] + bias[e])
#pragma unroll
    for (int i = 0; i < 16; i++) {
        int idx = tid + i * 256;
        int row = idx >> 6;
        int c4 = (idx & 63) * 4;
        float4 xv = *(const float4*)(x + (size_t)s_tok[row] * ND + c4);
        float4 bv = *(const float4*)(bias + (size_t)e * ND + c4);
        uint32_t p0 = packh(__float2half_rn(xv.x + bv.x), __float2half_rn(xv.y + bv.y));
        uint32_t p1 = packh(__float2half_rn(xv.z + bv.z), __float2half_rn(xv.w + bv.w));
        *(uint2*)(s_xb + row * XLDH + c4) = make_uint2(p0, p1);
    }
    __syncthreads();

    float acc[4][4][4];
#pragma unroll
    for (int mt = 0; mt < 4; mt++)
#pragma unroll
        for (int nt = 0; nt < 4; nt++)
#pragma unroll
            for (int i = 0; i < 4; i++) acc[mt][nt][i] = 0.f;

    // GEMM1: he = relu(xb @ W1[e] + b1[e])
    expert_mm16((const uint32_t*)s_xb, s_w, W1T + (size_t)e * ND * NH, acc, tid, g, cq, wn);
#pragma unroll
    for (int mt = 0; mt < 4; mt++) {
#pragma unroll
        for (int nt = 0; nt < 4; nt++) {
            int r = mt * 16 + g;
            int c = wn + nt * 8 + cq * 2;
            float bb0 = b1[(size_t)e * NH + c];
            float bb1 = b1[(size_t)e * NH + c + 1];
            float v0 = fmaxf(acc[mt][nt][0] + bb0, 0.f);
            float v1 = fmaxf(acc[mt][nt][1] + bb1, 0.f);
            float v2 = fmaxf(acc[mt][nt][2] + bb0, 0.f);
            float v3 = fmaxf(acc[mt][nt][3] + bb1, 0.f);
            *(uint32_t*)(s_he + r * XLDH + c) =
                packh(__float2half_rn(v0), __float2half_rn(v1));
            *(uint32_t*)(s_he + (r + 8) * XLDH + c) =
                packh(__float2half_rn(v2), __float2half_rn(v3));
        }
    }
    __syncthreads();

#pragma unroll
    for (int mt = 0; mt < 4; mt++)
#pragma unroll
        for (int nt = 0; nt < 4; nt++)
#pragma unroll
            for (int i = 0; i < 4; i++) acc[mt][nt][i] = 0.f;

    // GEMM2: out = (he @ W2[e] + b2[e]) * gate_w -> atomicAdd into y
    expert_mm16((const uint32_t*)s_he, s_w, W2T + (size_t)e * NH * NO, acc, tid, g, cq, wn);
#pragma unroll
    for (int mt = 0; mt < 4; mt++) {
#pragma unroll
        for (int nt = 0; nt < 4; nt++) {
            int r = mt * 16 + g;
            int c = wn + nt * 8 + cq * 2;
            float bb0 = b2[(size_t)e * NO + c];
            float bb1 = b2[(size_t)e * NO + c + 1];
            if (r < valid) {
                float gw = s_gw[r];
                float* yb = y + (size_t)s_tok[r] * NO + c;
                atomicAdd(yb,     (acc[mt][nt][0] + bb0) * gw);
                atomicAdd(yb + 1, (acc[mt][nt][1] + bb1) * gw);
            }
            int r2 = r + 8;
            if (r2 < valid) {
                float gw = s_gw[r2];
                float* yb = y + (size_t)s_tok[r2] * NO + c;
                atomicAdd(yb,     (acc[mt][nt][2] + bb0) * gw);
                atomicAdd(yb + 1, (acc[mt][nt][3] + bb1) * gw);
            }
        }
    }
}

// ---------------- launch ----------------
extern "C" void kernel_launch(void* const* d_in, const int* in_sizes, int n_in,
                              void* d_out, int out_size) {
    const float* x    = (const float*)d_in[0];
    const float* bias = (const float*)d_in[1];
    const float* W1   = (const float*)d_in[2];
    const float* b1   = (const float*)d_in[3];
    const float* W2   = (const float*)d_in[4];
    const float* b2   = (const float*)d_in[5];
    const float* g1   = (const float*)d_in[6];
    const float* gb1  = (const float*)d_in[7];
    const float* g2   = (const float*)d_in[8];
    const float* gb2  = (const float*)d_in[9];
    const float* g3   = (const float*)d_in[10];
    const float* gb3  = (const float*)d_in[11];

    float* yout = (float*)d_out;
    float* pout = yout + (size_t)NB * NO;

    __half *xh, *xl, *h1h, *h1l, *B1h, *B1l, *B2h, *B2l, *W1T, *W2T;
    float* h2p;
    cudaGetSymbolAddress((void**)&xh, g_xh);   cudaGetSymbolAddress((void**)&xl, g_xl);
    cudaGetSymbolAddress((void**)&h1h, g_h1h); cudaGetSymbolAddress((void**)&h1l, g_h1l);
    cudaGetSymbolAddress((void**)&B1h, g_B1h); cudaGetSymbolAddress((void**)&B1l, g_B1l);
    cudaGetSymbolAddress((void**)&B2h, g_B2h); cudaGetSymbolAddress((void**)&B2l, g_B2l);
    cudaGetSymbolAddress((void**)&W1T, g_W1T); cudaGetSymbolAddress((void**)&W2T, g_W2T);
    cudaGetSymbolAddress((void**)&h2p, g_h2);

    cudaFuncSetAttribute(gate_fp16<ND, NG, true>,
                         cudaFuncAttributeMaxDynamicSharedMemorySize, GATE_SMEM);
    cudaFuncSetAttribute(gate_fp16<NG, ND, false>,
                         cudaFuncAttributeMaxDynamicSharedMemorySize, GATE_SMEM);
    cudaFuncSetAttribute(expert_kernel,
                         cudaFuncAttributeMaxDynamicSharedMemorySize, EXP_SMEM);

    cudaMemsetAsync(yout, 0, (size_t)NB * NO * sizeof(float), 0);
    zero_counts_kernel<<<1, 32>>>();

    // prep: split x; transpose+split gate weights; transpose+convert expert weights
    split_x_kernel<<<NB * ND / 4 / 256, 256>>>(x);
    prep_w_kernel<<<NG * ND / 256, 256>>>(g1, B1h, B1l, ND, NG);
    prep_w_kernel<<<NG * ND / 256, 256>>>(g2, B2h, B2l, NG, ND);
    prep_ew_kernel<<<NE * NH * ND / 256, 256>>>(W1, W1T);
    prep_ew_kernel<<<NE * NO * NH / 256, 256>>>(W2, W2T);

    // gate MLP: fp16 3-product mma.sync (tf32x3-equivalent precision)
    gate_fp16<ND, NG, true><<<dim3(NG / 128, NB / 128), 256, GATE_SMEM>>>(
        xh, xl, B1h, B1l, gb1, (uint32_t*)h1h, (uint32_t*)h1l, nullptr);
    gate_fp16<NG, ND, false><<<dim3(ND / 128, NB / 128), 256, GATE_SMEM>>>(
        h1h, h1l, B2h, B2l, gb2, nullptr, nullptr, h2p);
    gate3_kernel<<<NB / 8, 256>>>(h2p, g3, gb3, pout);

    // routing
    scan_kernel<<<1, 32>>>();
    scatter_kernel<<<NB / 256, 256>>>();

    // top-2 expert compute (exact vs dense reference: p is 0 outside top-2)
    expert_kernel<<<dim3(NB / 64, NE), 256, EXP_SMEM>>>(
        x, bias, W1T, b1, W2T, b2, yout);
}

// round 10
// speedup vs baseline: 2.2876x; 1.0014x over previous
#include <cuda_runtime.h>
#include <cuda_fp16.h>
#include <cstdint>
#include <stdint.h>
#include <math.h>

#define NB 65536
#define ND 256
#define NE 16
#define NH 256
#define NO 256
#define NG 1024

// ---------------- scratch (device globals; no allocations allowed) ----------------
__device__ __align__(16) __half g_xh[(size_t)NB * ND], g_xl[(size_t)NB * ND];
__device__ __align__(16) __half g_h1h[(size_t)NB * NG], g_h1l[(size_t)NB * NG];
__device__ float  g_h2[(size_t)NB * ND];
__device__ __align__(16) __half g_B1h[NG * ND], g_B1l[NG * ND];   // [1024][256] K-major
__device__ __align__(16) __half g_B2h[ND * NG], g_B2l[ND * NG];   // [256][1024] K-major
__device__ __align__(16) __half g_W1T[NE * NH * ND];  // [e][h][d] K-major fp16
__device__ __align__(16) __half g_W2T[NE * NO * NH];  // [e][o][h] K-major fp16
__device__ int   g_e0[NB], g_e1[NB];
__device__ float g_w0[NB], g_w1[NB];
__device__ int   g_counts[NE], g_offsets[NE], g_cursor[NE];
__device__ int   g_ptok[2 * NB];
__device__ float g_pw[2 * NB];

__global__ void zero_counts_kernel() {
    if (threadIdx.x < NE) g_counts[threadIdx.x] = 0;
}

// ---------------- fp16 helpers ----------------
__device__ __forceinline__ uint32_t packh(__half a, __half b) {
    return ((uint32_t)__half_as_ushort(b) << 16) | (uint32_t)__half_as_ushort(a);
}
__device__ __forceinline__ void split2(float v, __half& h, __half& l) {
    h = __float2half_rn(v);
    l = __float2half_rn(v - __half2float(h));
}
__device__ __forceinline__ void mma_f16(float c[4], const uint32_t a[4], const uint32_t b[2]) {
    asm volatile(
        "mma.sync.aligned.m16n8k16.row.col.f32.f16.f16.f32 "
        "{%0,%1,%2,%3},{%4,%5,%6,%7},{%8,%9},{%0,%1,%2,%3};"
        : "+f"(c[0]), "+f"(c[1]), "+f"(c[2]), "+f"(c[3])
        : "r"(a[0]), "r"(a[1]), "r"(a[2]), "r"(a[3]), "r"(b[0]), "r"(b[1]));
}

// ---------------- prep kernels ----------------
__global__ __launch_bounds__(256) void split_x_kernel(const float* __restrict__ x) {
    size_t i = (size_t)blockIdx.x * 256 + threadIdx.x;   // per float4
    float4 v = ((const float4*)x)[i];
    __half h[4], l[4];
    split2(v.x, h[0], l[0]); split2(v.y, h[1], l[1]);
    split2(v.z, h[2], l[2]); split2(v.w, h[3], l[3]);
    ((uint2*)g_xh)[i] = make_uint2(packh(h[0], h[1]), packh(h[2], h[3]));
    ((uint2*)g_xl)[i] = make_uint2(packh(l[0], l[1]), packh(l[2], l[3]));
}

// out[n*K+k] = split(W[k*N+n])   (gate weights, 2-plane split)
__global__ __launch_bounds__(256) void prep_w_kernel(
    const float* __restrict__ W, __half* __restrict__ oh, __half* __restrict__ ol,
    int K, int N) {
    int idx = blockIdx.x * 256 + threadIdx.x;
    int n = idx / K, k = idx - n * K;
    float v = W[(size_t)k * N + n];
    __half h, l;
    split2(v, h, l);
    oh[idx] = h; ol[idx] = l;
}

// expert weights: WT[e][n][k] = (half) W[e][k][n],  K=N=256
__global__ __launch_bounds__(256) void prep_ew_kernel(
    const float* __restrict__ W, __half* __restrict__ WT) {
    int idx = blockIdx.x * 256 + threadIdx.x;      // e*65536 + k*256 + n
    int e = idx >> 16, rem = idx & 65535;
    int k = rem >> 8, n = rem & 255;
    WT[(size_t)e * 65536 + n * 256 + k] = __float2half_rn(W[idx]);
}

// ---------------- gate GEMM: C = relu(A@B^T + bias), fp16 3-product -----------------
// A planes [M][K], B planes [N][K] fp16 K-major. BM=128 BN=128 BK=32.
// Double-buffered smem (4 planes x [128][20] words), register prefetch, 1 sync/iter.
#define GSEG (128 * 20)
#define GATE_SMEM (2 * 4 * GSEG * 4)   // 81920 B

template<int K, int OUTW, bool SPLIT_OUT>
__global__ __launch_bounds__(256, 2) void gate_fp16(
    const __half* __restrict__ Ah_, const __half* __restrict__ Al_,
    const __half* __restrict__ Bh_, const __half* __restrict__ Bl_,
    const float* __restrict__ bias,
    uint32_t* __restrict__ Oh32, uint32_t* __restrict__ Ol32,
    float* __restrict__ Of) {
    extern __shared__ uint32_t gsm[];
    const int tid = threadIdx.x, lane = tid & 31, warp = tid >> 5;
    const int g = lane >> 2, cq = lane & 3;
    const int wm = (warp & 1) * 64, wn = (warp >> 1) * 32;
    const size_t bm = (size_t)blockIdx.y * 128;
    const size_t bn = (size_t)blockIdx.x * 128;

    float acc[4][4][4];
#pragma unroll
    for (int mt = 0; mt < 4; mt++)
#pragma unroll
        for (int nt = 0; nt < 4; nt++)
#pragma unroll
            for (int i = 0; i < 4; i++) acc[mt][nt][i] = 0.f;

    uint4 pAh[2], pAl[2], pBh[2], pBl[2];
    auto ldg = [&](int kt) {
#pragma unroll
        for (int i = 0; i < 2; i++) {
            const int idx = tid * 2 + i;
            const int row = idx >> 2;
            const int q = (idx & 3) * 8;   // halves
            const size_t ao = (bm + row) * (size_t)K + kt * 32 + q;
            const size_t bo = (bn + row) * (size_t)K + kt * 32 + q;
            pAh[i] = *(const uint4*)(Ah_ + ao);
            pAl[i] = *(const uint4*)(Al_ + ao);
            pBh[i] = *(const uint4*)(Bh_ + bo);
            pBl[i] = *(const uint4*)(Bl_ + bo);
        }
    };
    auto sts = [&](int buf) {
        uint32_t* base = gsm + buf * 4 * GSEG;
#pragma unroll
        for (int i = 0; i < 2; i++) {
            const int idx = tid * 2 + i;
            const int off = (idx >> 2) * 20 + (idx & 3) * 4;
            *(uint4*)&base[0 * GSEG + off] = pAh[i];
            *(uint4*)&base[1 * GSEG + off] = pAl[i];
            *(uint4*)&base[2 * GSEG + off] = pBh[i];
            *(uint4*)&base[3 * GSEG + off] = pBl[i];
        }
    };

    ldg(0); sts(0);
    __syncthreads();

    const int NCH = K / 32;
    for (int kt = 0; kt < NCH; kt++) {
        if (kt + 1 < NCH) ldg(kt + 1);
        const uint32_t* SAh = gsm + (kt & 1) * 4 * GSEG;
        const uint32_t* SAl = SAh + GSEG;
        const uint32_t* SBh = SAh + 2 * GSEG;
        const uint32_t* SBl = SAh + 3 * GSEG;
#pragma unroll
        for (int s = 0; s < 2; s++) {
            const int ks = s * 8;   // word offset in 20-word row
            uint32_t bh[4][2], bl[4][2];
#pragma unroll
            for (int nt = 0; nt < 4; nt++) {
                const int n = wn + nt * 8 + g;
                bh[nt][0] = SBh[n * 20 + ks + cq];
                bh[nt][1] = SBh[n * 20 + ks + cq + 4];
                bl[nt][0] = SBl[n * 20 + ks + cq];
                bl[nt][1] = SBl[n * 20 + ks + cq + 4];
            }
#pragma unroll
            for (int mt = 0; mt < 4; mt++) {
                const int r0 = wm + mt * 16 + g;
                uint32_t ah[4], al[4];
                ah[0] = SAh[r0 * 20 + ks + cq];       ah[1] = SAh[(r0 + 8) * 20 + ks + cq];
                ah[2] = SAh[r0 * 20 + ks + cq + 4];   ah[3] = SAh[(r0 + 8) * 20 + ks + cq + 4];
                al[0] = SAl[r0 * 20 + ks + cq];       al[1] = SAl[(r0 + 8) * 20 + ks + cq];
                al[2] = SAl[r0 * 20 + ks + cq + 4];   al[3] = SAl[(r0 + 8) * 20 + ks + cq + 4];
#pragma unroll
                for (int nt = 0; nt < 4; nt++) {
                    mma_f16(acc[mt][nt], al, bh[nt]);   // l*h
                    mma_f16(acc[mt][nt], ah, bl[nt]);   // h*l
                    mma_f16(acc[mt][nt], ah, bh[nt]);   // h*h
                }
            }
        }
        if (kt + 1 < NCH) sts((kt + 1) & 1);
        __syncthreads();
    }

    // epilogue
#pragma unroll
    for (int mt = 0; mt < 4; mt++) {
#pragma unroll
        for (int nt = 0; nt < 4; nt++) {
            const size_t r0 = bm + wm + mt * 16 + g;
            const int c = (int)bn + wn + nt * 8 + cq * 2;
            const float b0 = __ldg(&bias[c]), b1 = __ldg(&bias[c + 1]);
            float v0 = fmaxf(acc[mt][nt][0] + b0, 0.f);
            float v1 = fmaxf(acc[mt][nt][1] + b1, 0.f);
            float v2 = fmaxf(acc[mt][nt][2] + b0, 0.f);
            float v3 = fmaxf(acc[mt][nt][3] + b1, 0.f);
            if (SPLIT_OUT) {
                __half h0, l0, h1, l1, h2, l2, h3, l3;
                split2(v0, h0, l0); split2(v1, h1, l1);
                split2(v2, h2, l2); split2(v3, h3, l3);
                Oh32[r0 * (OUTW / 2) + (c >> 1)]       = packh(h0, h1);
                Ol32[r0 * (OUTW / 2) + (c >> 1)]       = packh(l0, l1);
                Oh32[(r0 + 8) * (OUTW / 2) + (c >> 1)] = packh(h2, h3);
                Ol32[(r0 + 8) * (OUTW / 2) + (c >> 1)] = packh(l2, l3);
            } else {
                *(float2*)(Of + r0 * OUTW + c)       = make_float2(v0, v1);
                *(float2*)(Of + (r0 + 8) * OUTW + c) = make_float2(v2, v3);
            }
        }
    }
}

// ---------------- gate head: logits -> softmax -> top2 -> p + routing (fp32) -------
__global__ __launch_bounds__(256) void gate3_kernel(
    const float* __restrict__ h2, const float* __restrict__ g3,
    const float* __restrict__ gb3, float* __restrict__ p_out) {
    __shared__ float sg3t[16][260];
    __shared__ float sh2[8][256];
    const int tid = threadIdx.x;
    const int warp = tid >> 5, lane = tid & 31;

    for (int idx = tid; idx < ND * NE; idx += 256)
        sg3t[idx & 15][idx >> 4] = g3[idx];

    const int t = blockIdx.x * 8 + warp;
    const float4* hrow = (const float4*)(h2 + (size_t)t * ND);
    for (int i = lane; i < ND / 4; i += 32)
        *(float4*)&sh2[warp][i * 4] = hrow[i];
    __syncthreads();

    const int e = lane & 15, half = lane >> 4;
    const float* hp = &sh2[warp][half * 128];
    const float* gp = &sg3t[e][half * 128];
    float s = 0.f;
#pragma unroll 8
    for (int k4 = 0; k4 < 32; k4++) {
        float4 hv = *(const float4*)(hp + k4 * 4);
        float4 gv = *(const float4*)(gp + k4 * 4);
        s += hv.x * gv.x + hv.y * gv.y + hv.z * gv.z + hv.w * gv.w;
    }
    s += __shfl_xor_sync(0xffffffffu, s, 16);
    float logit = (lane < 16) ? s + gb3[e] : -1e30f;

    float mx = logit;
#pragma unroll
    for (int m = 8; m >= 1; m >>= 1)
        mx = fmaxf(mx, __shfl_xor_sync(0xffffffffu, mx, m, 16));
    float ex = expf(logit - mx);
    float sum = ex;
#pragma unroll
    for (int m = 8; m >= 1; m >>= 1)
        sum += __shfl_xor_sync(0xffffffffu, sum, m, 16);
    float pv = ex / sum;

    float v1 = pv; int i1 = e;
#pragma unroll
    for (int m = 8; m >= 1; m >>= 1) {
        float ov = __shfl_xor_sync(0xffffffffu, v1, m, 16);
        int   oi = __shfl_xor_sync(0xffffffffu, i1, m, 16);
        if (ov > v1 || (ov == v1 && oi < i1)) { v1 = ov; i1 = oi; }
    }
    float c2 = (e == i1) ? -1.f : pv;
    float v2 = c2; int i2 = e;
#pragma unroll
    for (int m = 8; m >= 1; m >>= 1) {
        float ov = __shfl_xor_sync(0xffffffffu, v2, m, 16);
        int   oi = __shfl_xor_sync(0xffffffffu, i2, m, 16);
        if (ov > v2 || (ov == v2 && oi < i2)) { v2 = ov; i2 = oi; }
    }
    float inv = 1.f / (v1 + v2 + 1e-9f);
    if (lane < 16) {
        float po = 0.f;
        if (e == i1) po = v1 * inv;
        else if (e == i2) po = v2 * inv;
        p_out[(size_t)t * NE + e] = po;
    }
    if (lane == 0) {
        g_e0[t] = i1; g_e1[t] = i2;
        g_w0[t] = v1 * inv; g_w1[t] = v2 * inv;
        atomicAdd(&g_counts[i1], 1);
        atomicAdd(&g_counts[i2], 1);
    }
}

__global__ void scan_kernel() {
    if (threadIdx.x == 0) {
        int off = 0;
#pragma unroll
        for (int e = 0; e < NE; e++) {
            g_offsets[e] = off;
            g_cursor[e] = off;
            off += g_counts[e];
        }
    }
}

__global__ __launch_bounds__(256) void scatter_kernel() {
    int t = blockIdx.x * 256 + threadIdx.x;
    int e0 = g_e0[t], e1 = g_e1[t];
    int p0 = atomicAdd(&g_cursor[e0], 1);
    g_ptok[p0] = t; g_pw[p0] = g_w0[t];
    int p1 = atomicAdd(&g_cursor[e1], 1);
    g_ptok[p1] = t; g_pw[p1] = g_w1[t];
}

// ---------------- expert kernel: 64-token tile, fp16 mma, fused 2 GEMMs ------------
// activations fp16 smem [64][264]; weights pre-transposed fp16 [e][n][k];
// W tile smem [256][20 words], double-buffered.
#define XLDH 264                    // halves per act row (word stride 132)
#define EWRD 20                     // words per W row
#define EXP_SMEM (2 * 64 * XLDH * 2 + 2 * 256 * EWRD * 4)   // 108544 B

__device__ __forceinline__ void expert_mm16(
    const uint32_t* __restrict__ sa, uint32_t* __restrict__ sw,
    const __half* __restrict__ WT, float acc[4][4][4],
    int tid, int g, int cq, int wn) {
    uint4 pw[4];
    // one chunk = 256 rows x 32 halves = 1024 uint4 -> 4 per thread
    auto ldw = [&](int kc) {
#pragma unroll
        for (int i = 0; i < 4; i++) {
            const int idx = tid + i * 256;
            const int n = idx >> 2;
            const int q = (idx & 3) * 8;
            pw[i] = *(const uint4*)(WT + n * 256 + kc * 32 + q);
        }
    };
    auto stw = [&](int buf) {
#pragma unroll
        for (int i = 0; i < 4; i++) {
            const int idx = tid + i * 256;
            *(uint4*)&sw[buf * 256 * EWRD + (idx >> 2) * EWRD + (idx & 3) * 4] = pw[i];
        }
    };
    ldw(0); stw(0);
    __syncthreads();
    for (int kc = 0; kc < 8; kc++) {
        if (kc + 1 < 8) ldw(kc + 1);
        const uint32_t* W_s = sw + (kc & 1) * 256 * EWRD;
#pragma unroll
        for (int s = 0; s < 2; s++) {
            const int ks = s * 8;                 // word offset in W row
            const int ka = kc * 16 + s * 8;       // word offset in act row
            uint32_t bf[4][2];
#pragma unroll
            for (int nt = 0; nt < 4; nt++) {
                const int n = wn + nt * 8 + g;
                bf[nt][0] = W_s[n * EWRD + ks + cq];
                bf[nt][1] = W_s[n * EWRD + ks + cq + 4];
            }
#pragma unroll
            for (int mt = 0; mt < 4; mt++) {
                const int r0 = mt * 16 + g;
                uint32_t af[4];
                af[0] = sa[r0 * 132 + ka + cq];
                af[1] = sa[(r0 + 8) * 132 + ka + cq];
                af[2] = sa[r0 * 132 + ka + cq + 4];
                af[3] = sa[(r0 + 8) * 132 + ka + cq + 4];
#pragma unroll
                for (int nt = 0; nt < 4; nt++)
                    mma_f16(acc[mt][nt], af, bf[nt]);
            }
        }
        if (kc + 1 < 8) stw((kc + 1) & 1);
        __syncthreads();
    }
}

__global__ __launch_bounds__(256) void expert_kernel(
    const float* __restrict__ x, const float* __restrict__ bias,
    const __half* __restrict__ W1T, const float* __restrict__ b1,
    const __half* __restrict__ W2T, const float* __restrict__ b2,
    float* __restrict__ y) {
    const int e = blockIdx.y;
    const int cnt = g_counts[e];
    const int start = blockIdx.x * 64;
    if (start >= cnt) return;
    const int base = g_offsets[e];
    const int valid = min(64, cnt - start);

    extern __shared__ char esm[];
    __half* s_xb = (__half*)esm;                        // [64][264]
    __half* s_he = s_xb + 64 * XLDH;                    // [64][264]
    uint32_t* s_w = (uint32_t*)(s_he + 64 * XLDH);      // 2 x [256][20]
    __shared__ int   s_tok[64];
    __shared__ float s_gw[64];

    const int tid = threadIdx.x, lane = tid & 31;
    const int g = lane >> 2, cq = lane & 3;
    const int wn = (tid >> 5) * 32;

    if (tid < 64) {
        int tok = 0; float w = 0.f;
        if (tid < valid) { tok = g_ptok[base + start + tid]; w = g_pw[base + start + tid]; }
        s_tok[tid] = tok; s_gw[tid] = w;
    }
    __syncthreads();

    // gather xb = half(x[tok] + bias[e])
#pragma unroll
    for (int i = 0; i < 16; i++) {
        int idx = tid + i * 256;
        int row = idx >> 6;
        int c4 = (idx & 63) * 4;
        float4 xv = *(const float4*)(x + (size_t)s_tok[row] * ND + c4);
        float4 bv = *(const float4*)(bias + (size_t)e * ND + c4);
        uint32_t p0 = packh(__float2half_rn(xv.x + bv.x), __float2half_rn(xv.y + bv.y));
        uint32_t p1 = packh(__float2half_rn(xv.z + bv.z), __float2half_rn(xv.w + bv.w));
        *(uint2*)(s_xb + row * XLDH + c4) = make_uint2(p0, p1);
    }
    __syncthreads();

    float acc[4][4][4];
#pragma unroll
    for (int mt = 0; mt < 4; mt++)
#pragma unroll
        for (int nt = 0; nt < 4; nt++)
#pragma unroll
            for (int i = 0; i < 4; i++) acc[mt][nt][i] = 0.f;

    // GEMM1: he = relu(xb @ W1[e] + b1[e])
    expert_mm16((const uint32_t*)s_xb, s_w, W1T + (size_t)e * ND * NH, acc, tid, g, cq, wn);
#pragma unroll
    for (int mt = 0; mt < 4; mt++) {
#pragma unroll
        for (int nt = 0; nt < 4; nt++) {
            int r = mt * 16 + g;
            int c = wn + nt * 8 + cq * 2;
            float bb0 = b1[(size_t)e * NH + c];
            float bb1 = b1[(size_t)e * NH + c + 1];
            float v0 = fmaxf(acc[mt][nt][0] + bb0, 0.f);
            float v1 = fmaxf(acc[mt][nt][1] + bb1, 0.f);
            float v2 = fmaxf(acc[mt][nt][2] + bb0, 0.f);
            float v3 = fmaxf(acc[mt][nt][3] + bb1, 0.f);
            *(uint32_t*)(s_he + r * XLDH + c) =
                packh(__float2half_rn(v0), __float2half_rn(v1));
            *(uint32_t*)(s_he + (r + 8) * XLDH + c) =
                packh(__float2half_rn(v2), __float2half_rn(v3));
        }
    }
    __syncthreads();

#pragma unroll
    for (int mt = 0; mt < 4; mt++)
#pragma unroll
        for (int nt = 0; nt < 4; nt++)
#pragma unroll
            for (int i = 0; i < 4; i++) acc[mt][nt][i] = 0.f;

    // GEMM2: out = (he @ W2[e] + b2[e]) * gate_w -> atomicAdd into y
    expert_mm16((const uint32_t*)s_he, s_w, W2T + (size_t)e * NH * NO, acc, tid, g, cq, wn);
#pragma unroll
    for (int mt = 0; mt < 4; mt++) {
#pragma unroll
        for (int nt = 0; nt < 4; nt++) {
            int r = mt * 16 + g;
            int c = wn + nt * 8 + cq * 2;
            float bb0 = b2[(size_t)e * NO + c];
            float bb1 = b2[(size_t)e * NO + c + 1];
            if (r < valid) {
                float gw = s_gw[r];
                float* yb = y + (size_t)s_tok[r] * NO + c;
                atomicAdd(yb,     (acc[mt][nt][0] + bb0) * gw);
                atomicAdd(yb + 1, (acc[mt][nt][1] + bb1) * gw);
            }
            int r2 = r + 8;
            if (r2 < valid) {
                float gw = s_gw[r2];
                float* yb = y + (size_t)s_tok[r2] * NO + c;
                atomicAdd(yb,     (acc[mt][nt][2] + bb0) * gw);
                atomicAdd(yb + 1, (acc[mt][nt][3] + bb1) * gw);
            }
        }
    }
}

// ---------------- launch ----------------
extern "C" void kernel_launch(void* const* d_in, const int* in_sizes, int n_in,
                              void* d_out, int out_size) {
    const float* x    = (const float*)d_in[0];
    const float* bias = (const float*)d_in[1];
    const float* W1   = (const float*)d_in[2];
    const float* b1   = (const float*)d_in[3];
    const float* W2   = (const float*)d_in[4];
    const float* b2   = (const float*)d_in[5];
    const float* g1   = (const float*)d_in[6];
    const float* gb1  = (const float*)d_in[7];
    const float* g2   = (const float*)d_in[8];
    const float* gb2  = (const float*)d_in[9];
    const float* g3   = (const float*)d_in[10];
    const float* gb3  = (const float*)d_in[11];

    float* yout = (float*)d_out;
    float* pout = yout + (size_t)NB * NO;

    __half *xh, *xl, *h1h, *h1l, *B1h, *B1l, *B2h, *B2l, *W1T, *W2T;
    float* h2p;
    cudaGetSymbolAddress((void**)&xh, g_xh);   cudaGetSymbolAddress((void**)&xl, g_xl);
    cudaGetSymbolAddress((void**)&h1h, g_h1h); cudaGetSymbolAddress((void**)&h1l, g_h1l);
    cudaGetSymbolAddress((void**)&B1h, g_B1h); cudaGetSymbolAddress((void**)&B1l, g_B1l);
    cudaGetSymbolAddress((void**)&B2h, g_B2h); cudaGetSymbolAddress((void**)&B2l, g_B2l);
    cudaGetSymbolAddress((void**)&W1T, g_W1T); cudaGetSymbolAddress((void**)&W2T, g_W2T);
    cudaGetSymbolAddress((void**)&h2p, g_h2);

    cudaFuncSetAttribute(gate_fp16<ND, NG, true>,
                         cudaFuncAttributeMaxDynamicSharedMemorySize, GATE_SMEM);
    cudaFuncSetAttribute(gate_fp16<NG, ND, false>,
                         cudaFuncAttributeMaxDynamicSharedMemorySize, GATE_SMEM);
    cudaFuncSetAttribute(expert_kernel,
                         cudaFuncAttributeMaxDynamicSharedMemorySize, EXP_SMEM);

    cudaMemsetAsync(yout, 0, (size_t)NB * NO * sizeof(float), 0);
    zero_counts_kernel<<<1, 32>>>();

    // prep: split x; transpose+split gate weights; transpose+convert expert weights
    split_x_kernel<<<NB * ND / 4 / 256, 256>>>(x);
    prep_w_kernel<<<NG * ND / 256, 256>>>(g1, B1h, B1l, ND, NG);
    prep_w_kernel<<<NG * ND / 256, 256>>>(g2, B2h, B2l, NG, ND);
    prep_ew_kernel<<<NE * NH * ND / 256, 256>>>(W1, W1T);
    prep_ew_kernel<<<NE * NO * NH / 256, 256>>>(W2, W2T);

    // gate MLP: fp16 3-product mma.sync (tf32x3-equivalent precision)
    gate_fp16<ND, NG, true><<<dim3(NG / 128, NB / 128), 256, GATE_SMEM>>>(
        xh, xl, B1h, B1l, gb1, (uint32_t*)h1h, (uint32_t*)h1l, nullptr);
    gate_fp16<NG, ND, false><<<dim3(ND / 128, NB / 128), 256, GATE_SMEM>>>(
        h1h, h1l, B2h, B2l, gb2, nullptr, nullptr, h2p);
    gate3_kernel<<<NB / 8, 256>>>(h2p, g3, gb3, pout);

    // routing
    scan_kernel<<<1, 32>>>();
    scatter_kernel<<<NB / 256, 256>>>();

    // top-2 expert compute (exact vs dense reference: p is 0 outside top-2)
    expert_kernel<<<dim3(NB / 64, NE), 256, EXP_SMEM>>>(
        x, bias, W1T, b1, W2T, b2, yout);
}